// round 13
// baseline (speedup 1.0000x reference)
#include <cuda_runtime.h>
#include <cuda_fp16.h>
#include <cstdint>
#include <math.h>

#define NV      6890
#define NPTS    16384
#define LDF     704

// ---- spatial grid for KNN ----
#define GRIDN   64
#define GRIDC   (GRIDN * GRIDN * GRIDN)
#define GLO     (-5.0f)
#define GH      0.15625f                 // 10/64
#define GINV    6.4f
#define CELLCAP 8
#define OVFCAP  2048

// ---------------- scratch (device globals) -----------------------------------
__device__ __align__(16) __half  g_featH[(size_t)NPTS * LDF];
__device__ __align__(16) __half  g_W1h[(size_t)256 * LDF];
__device__ __align__(16) __half  g_W2h[(size_t)256 * 256];
__device__ __align__(16) __half  g_W3h[(size_t)256 * 256];
__device__ float                 g_Rinv[NV * 9];
__device__ int                   g_knn[NPTS];
__device__ __align__(16) float4  g_cell[(size_t)GRIDC * CELLCAP];   // 16 MB
__device__ int                   g_ccnt[GRIDC];                     // memset 0
__device__ __align__(16) float4  g_ovf[OVFCAP];
__device__ int                   g_ovfn;                            // memset 0

// ======================= small PTX helpers ===================================
__device__ __forceinline__ uint32_t smem_u32(const void* p) {
    uint32_t a;
    asm("{ .reg .u64 t; cvta.to.shared.u64 t, %1; cvt.u32.u64 %0, t; }" : "=r"(a) : "l"(p));
    return a;
}
__device__ __forceinline__ void cpa16(uint32_t dst, const void* src) {
    asm volatile("cp.async.cg.shared.global [%0], [%1], 16;" :: "r"(dst), "l"(src));
}
#define CPA_COMMIT() asm volatile("cp.async.commit_group;" ::: "memory")

__device__ __forceinline__ void ldm4(uint32_t* r, uint32_t addr) {
    asm volatile("ldmatrix.sync.aligned.m8n8.x4.shared.b16 {%0,%1,%2,%3}, [%4];"
                 : "=r"(r[0]), "=r"(r[1]), "=r"(r[2]), "=r"(r[3]) : "r"(addr));
}
__device__ __forceinline__ void mma16816(float* c, const uint32_t* a, uint32_t b0, uint32_t b1) {
    asm volatile(
        "mma.sync.aligned.m16n8k16.row.col.f32.f16.f16.f32 "
        "{%0,%1,%2,%3}, {%4,%5,%6,%7}, {%8,%9}, {%0,%1,%2,%3};"
        : "+f"(c[0]), "+f"(c[1]), "+f"(c[2]), "+f"(c[3])
        : "r"(a[0]), "r"(a[1]), "r"(a[2]), "r"(a[3]), "r"(b0), "r"(b1));
}

// ---------------- accurate fp32 sincos (no FP64) -----------------------------
__device__ __forceinline__ void sincos_acc(float x, float* s, float* c) {
    const float C1 = 6.28125f;
    const float C2 = (float)1.9353071795864769e-3;
    const float C3 = (float)(6.283185307179586476925286766559 - 6.28125 -
                             (double)((float)1.9353071795864769e-3));
    float q = rintf(x * 0.15915494309189535f);
    float r = fmaf(q, -C1, x);
    r = fmaf(q, -C2, r);
    r = fmaf(q, -C3, r);
    sincosf(r, s, c);
}

// ============ kernel 1: setup (grid build | invert | transpose) ===============
// blocks [0,27): grid build; [27,54): invert; [54,358): weight transpose.
__global__ __launch_bounds__(256) void setup_kernel(
    const float* __restrict__ kp,
    const float* __restrict__ trans,
    const float* __restrict__ W1, const float* __restrict__ W2,
    const float* __restrict__ W3,
    __half* __restrict__ W1h, __half* __restrict__ W2h, __half* __restrict__ W3h)
{
    __shared__ float tile[32][33];
    const int b   = blockIdx.x;
    const int tid = threadIdx.x;

    if (b < 27) {
        // ---------------- grid build ----------------
        int v = b * 256 + tid;
        if (v >= NV) return;
        float kx = kp[v*3], ky = kp[v*3+1], kz = kp[v*3+2];
        int cx = (int)floorf((kx - GLO) * GINV);
        int cy = (int)floorf((ky - GLO) * GINV);
        int cz = (int)floorf((kz - GLO) * GINV);
        float4 rec = make_float4(kx, ky, kz, __int_as_float(v));
        if ((unsigned)cx < GRIDN && (unsigned)cy < GRIDN && (unsigned)cz < GRIDN) {
            int c = (cz * GRIDN + cy) * GRIDN + cx;
            int s = atomicAdd(&g_ccnt[c], 1);
            if (s < CELLCAP) {
                g_cell[(size_t)c * CELLCAP + s] = rec;
            } else {
                int o = atomicAdd(&g_ovfn, 1);
                if (o < OVFCAP) g_ovf[o] = rec;
            }
        } else {
            int o = atomicAdd(&g_ovfn, 1);
            if (o < OVFCAP) g_ovf[o] = rec;
        }

    } else if (b < 54) {
        // ---------------- invert 4x4 ----------------
        int v = (b - 27) * 256 + tid;
        if (v >= NV) return;
        float m[16];
#pragma unroll
        for (int k = 0; k < 16; k++) m[k] = trans[k * NV + v];

        float i0  =  m[5]*m[10]*m[15] - m[5]*m[11]*m[14] - m[9]*m[6]*m[15] + m[9]*m[7]*m[14] + m[13]*m[6]*m[11] - m[13]*m[7]*m[10];
        float i4  = -m[4]*m[10]*m[15] + m[4]*m[11]*m[14] + m[8]*m[6]*m[15] - m[8]*m[7]*m[14] - m[12]*m[6]*m[11] + m[12]*m[7]*m[10];
        float i8  =  m[4]*m[9]*m[15]  - m[4]*m[11]*m[13] - m[8]*m[5]*m[15] + m[8]*m[7]*m[13] + m[12]*m[5]*m[11] - m[12]*m[7]*m[9];
        float i12 = -m[4]*m[9]*m[14]  + m[4]*m[10]*m[13] + m[8]*m[5]*m[14] - m[8]*m[6]*m[13] - m[12]*m[5]*m[10] + m[12]*m[6]*m[9];
        float i1  = -m[1]*m[10]*m[15] + m[1]*m[11]*m[14] + m[9]*m[2]*m[15] - m[9]*m[3]*m[14] - m[13]*m[2]*m[11] + m[13]*m[3]*m[10];
        float i5  =  m[0]*m[10]*m[15] - m[0]*m[11]*m[14] - m[8]*m[2]*m[15] + m[8]*m[3]*m[14] + m[12]*m[2]*m[11] - m[12]*m[3]*m[10];
        float i9  = -m[0]*m[9]*m[15]  + m[0]*m[11]*m[13] + m[8]*m[1]*m[15] - m[8]*m[3]*m[13] - m[12]*m[1]*m[11] + m[12]*m[3]*m[9];
        float i2  =  m[1]*m[6]*m[15]  - m[1]*m[7]*m[14]  - m[5]*m[2]*m[15] + m[5]*m[3]*m[14] + m[13]*m[2]*m[7]  - m[13]*m[3]*m[6];
        float i6  = -m[0]*m[6]*m[15]  + m[0]*m[7]*m[14]  + m[4]*m[2]*m[15] - m[4]*m[3]*m[14] - m[12]*m[2]*m[7]  + m[12]*m[3]*m[6];
        float i10 =  m[0]*m[5]*m[15]  - m[0]*m[7]*m[13]  - m[4]*m[1]*m[15] + m[4]*m[3]*m[13] + m[12]*m[1]*m[7]  - m[12]*m[3]*m[5];

        float det = m[0]*i0 + m[1]*i4 + m[2]*i8 + m[3]*i12;
        float id  = 1.0f / det;
        float* R = g_Rinv + v * 9;
        R[0] = i0*id;  R[1] = i1*id;  R[2] = i2*id;
        R[3] = i4*id;  R[4] = i5*id;  R[5] = i6*id;
        R[6] = i8*id;  R[7] = i9*id;  R[8] = i10*id;

    } else {
        // ---------------- weight transpose to fp16 ----------------
        int u = b - 54;
        const float* W; __half* Wh; int K, ldk, kb, nb;
        if (u < 176)      { W = W1; Wh = W1h; K = 700; ldk = LDF; kb = (u % 22) * 32; nb = (u / 22) * 32; }
        else if (u < 240) { u -= 176; W = W2; Wh = W2h; K = 256; ldk = 256; kb = (u % 8) * 32; nb = (u / 8) * 32; }
        else              { u -= 240; W = W3; Wh = W3h; K = 256; ldk = 256; kb = (u % 8) * 32; nb = (u / 8) * 32; }

        int tx = tid & 31, ty = tid >> 5;
#pragma unroll
        for (int i = 0; i < 4; i++) {
            int k = kb + ty + i * 8;
            tile[ty + i * 8][tx] = (k < K) ? W[(size_t)k * 256 + nb + tx] : 0.0f;
        }
        __syncthreads();
#pragma unroll
        for (int i = 0; i < 4; i++) {
            int n = nb + ty + i * 8;
            Wh[(size_t)n * ldk + kb + tx] = __float2half_rn(tile[tx][ty + i * 8]);
        }
    }
}

// ============ kernel 2: grid KNN query (warp per point) ========================
__global__ __launch_bounds__(256) void knn_query(const float* __restrict__ pts) {
    const int gw   = (blockIdx.x * blockDim.x + threadIdx.x) >> 5;
    const int lane = threadIdx.x & 31;
    if (gw >= NPTS) return;

    const float px = pts[gw*6], py = pts[gw*6+1], pz = pts[gw*6+2];
    int cx = min(max((int)floorf((px - GLO) * GINV), 0), GRIDN - 1);
    int cy = min(max((int)floorf((py - GLO) * GINV), 0), GRIDN - 1);
    int cz = min(max((int)floorf((pz - GLO) * GINV), 0), GRIDN - 1);

    unsigned long long best = ~0ull;   // sentinel: d2 bits = 0xFFFFFFFF (> any valid d2)

    auto eval_cell = [&](int x, int y, int z) {
        if ((unsigned)x >= GRIDN || (unsigned)y >= GRIDN || (unsigned)z >= GRIDN) return;
        int c = (z * GRIDN + y) * GRIDN + x;
        int cnt = min(g_ccnt[c], CELLCAP);
        const float4* cd = &g_cell[(size_t)c * CELLCAP];
        for (int j = 0; j < cnt; j++) {
            float4 k = cd[j];
            float dx = px - k.x, dy = py - k.y, dz = pz - k.z;
            float d2 = fmaf(dx, dx, fmaf(dy, dy, dz * dz));
            unsigned long long pk =
                ((unsigned long long)__float_as_uint(d2) << 32) |
                (unsigned int)__float_as_int(k.w);
            if (pk < best) best = pk;
        }
    };

    // pass 1: radius-1 cube (27 cells; lane l -> one cell) + overflow list
    if (lane < 27) {
        eval_cell(cx + (lane % 3) - 1, cy + ((lane / 3) % 3) - 1, cz + (lane / 9) - 1);
    }
    {
        int n = min(g_ovfn, OVFCAP);
        for (int i = lane; i < n; i += 32) {
            float4 k = g_ovf[i];
            float dx = px - k.x, dy = py - k.y, dz = pz - k.z;
            float d2 = fmaf(dx, dx, fmaf(dy, dy, dz * dz));
            unsigned long long pk =
                ((unsigned long long)__float_as_uint(d2) << 32) |
                (unsigned int)__float_as_int(k.w);
            if (pk < best) best = pk;
        }
    }
    // warp reduce min
    unsigned long long o;
    o = __shfl_xor_sync(0xffffffffu, best, 1);  if (o < best) best = o;
    o = __shfl_xor_sync(0xffffffffu, best, 2);  if (o < best) best = o;
    o = __shfl_xor_sync(0xffffffffu, best, 4);  if (o < best) best = o;
    o = __shfl_xor_sync(0xffffffffu, best, 8);  if (o < best) best = o;
    o = __shfl_xor_sync(0xffffffffu, best, 16); if (o < best) best = o;

    // expansion gate in UINT bit-space: sentinel 0xFFFFFFFF (NaN bits) correctly
    // compares greater than every valid d2, forcing expansion when empty.
    uint32_t bd2bits = (uint32_t)(best >> 32);
    float guar = GH;
    if (bd2bits > __float_as_uint(guar * guar)) {
        for (int R = 2; R < GRIDN; R++) {
            int S = 2 * R + 1;
            int tot = S * S * S;
            for (int s = lane; s < tot; s += 32) {
                int dx = s % S - R;
                int dy = (s / S) % S - R;
                int dz = s / (S * S) - R;
                eval_cell(cx + dx, cy + dy, cz + dz);
            }
            o = __shfl_xor_sync(0xffffffffu, best, 1);  if (o < best) best = o;
            o = __shfl_xor_sync(0xffffffffu, best, 2);  if (o < best) best = o;
            o = __shfl_xor_sync(0xffffffffu, best, 4);  if (o < best) best = o;
            o = __shfl_xor_sync(0xffffffffu, best, 8);  if (o < best) best = o;
            o = __shfl_xor_sync(0xffffffffu, best, 16); if (o < best) best = o;
            bd2bits = (uint32_t)(best >> 32);
            float g = (float)R * GH;
            if (bd2bits <= __float_as_uint(g * g)) break;
        }
    }

    if (lane == 0) g_knn[gw] = (int)(best & 0xFFFFFFFFull);
}

// ---------------- kernel 3: feature build ------------------------------------
__global__ __launch_bounds__(256) void feat_kernel(const float* __restrict__ pts,
                                                   const float* __restrict__ kp,
                                                   const int*   __restrict__ nbr,
                                                   const float* __restrict__ rest,
                                                   const float* __restrict__ lat,
                                                   float*       __restrict__ out) {
    int gw   = (blockIdx.x * blockDim.x + threadIdx.x) >> 5;
    int lane = threadIdx.x & 31;
    if (gw >= NPTS) return;

    int kidx = g_knn[gw];

    float px = pts[gw*6], py = pts[gw*6+1], pz = pts[gw*6+2];

    int vj = (lane < 7) ? nbr[kidx*7 + lane] : 0;
    int j  = (lane < 21) ? (lane / 3) : ((lane < 28) ? (lane - 21) : 0);
    int v  = __shfl_sync(0xffffffffu, vj, j);

    float vf = 0.0f;
    if (lane < 21) {
        vf = rest[v*3 + (lane % 3)];
    } else if (lane < 28) {
        float dx = px - kp[v*3], dy = py - kp[v*3+1], dz = pz - kp[v*3+2];
        vf = sqrtf(dx*dx + dy*dy + dz*dz);
    }

    size_t base = (size_t)gw * LDF;
    if (lane < 28) {
        g_featH[base + lane] = __float2half_rn(vf);
        float s, c;
        sincos_acc(vf, &s, &c);
#pragma unroll
        for (int k = 0; k < 10; k++) {
            g_featH[base + 28  + k*28 + lane] = __float2half_rn(s);
            g_featH[base + 308 + k*28 + lane] = __float2half_rn(c);
            float sn = 2.0f * s * c;
            float cn = fmaf(-2.0f * s, s, 1.0f);
            s = sn; c = cn;
        }
    }
    if (lane < 4) g_featH[base + 700 + lane] = __float2half_rn(0.0f);

#pragma unroll
    for (int it = 0; it < 4; it++) {
        int l  = it * 32 + lane;
        int jj = (l < 112) ? (l >> 4) : 0;
        int vv = __shfl_sync(0xffffffffu, vj, jj);
        if (l < 112) g_featH[base + 588 + l] = __float2half_rn(lat[vv*16 + (l & 15)]);
    }

    if (lane == 0) {
        float dx = px - kp[kidx*3], dy = py - kp[kidx*3+1], dz = pz - kp[kidx*3+2];
        const float* R = g_Rinv + kidx * 9;
        float d0 = R[0]*dx + R[1]*dy + R[2]*dz;
        float d1 = R[3]*dx + R[4]*dy + R[5]*dz;
        float d2 = R[6]*dx + R[7]*dy + R[8]*dz;
        float nn = sqrtf(d0*d0 + d1*d1 + d2*d2);
        float iv = 1.0f / fmaxf(nn, 1e-12f);
        d0 *= iv; d1 *= iv; d2 *= iv;
        float* op = out + (size_t)gw * 283 + 256;
        op[0] = d0; op[1] = d1; op[2] = d2;
        float dir[3] = {d0, d1, d2};
#pragma unroll
        for (int c = 0; c < 3; c++) {
            float s, cc;
            sincos_acc(dir[c], &s, &cc);
#pragma unroll
            for (int k = 0; k < 4; k++) {
                op[3  + k*3 + c] = s;
                op[15 + k*3 + c] = cc;
                float sn = 2.0f * s * cc;
                float cn = fmaf(-2.0f * s, s, 1.0f);
                s = sn; cc = cn;
            }
        }
    }
}

// ---------------- kernel 4: fused 3-layer MLP (fp16 HMMA) --------------------
#define PADH    40
#define ATILE   (128 * PADH * 2)
#define BTILE   (256 * PADH * 2)
#define BUFB    (ATILE + BTILE)
#define SM_H    (2 * BUFB)
#define HCHUNK  (128 * PADH)
#define MLP_SMEM (SM_H + 8 * HCHUNK * 2)   // 143360 B

__global__ __launch_bounds__(512, 1) void mlp_fused(
    const __half* __restrict__ feat,
    const __half* __restrict__ W1, const __half* __restrict__ W2,
    const __half* __restrict__ W3,
    const float* __restrict__ b1, const float* __restrict__ b2,
    const float* __restrict__ b3,
    float* __restrict__ out)
{
    extern __shared__ char sm[];
    const int tid  = threadIdx.x;
    const int wid  = tid >> 5, lane = tid & 31;
    const int g    = lane >> 2, t = lane & 3;
    const int m0   = blockIdx.x * 128;
    const int m0w  = (wid >> 2) * 32, n0w = (wid & 3) * 64;
    const uint32_t smb = smem_u32(sm);
    const uint32_t sH  = smb + SM_H;
    __half* Hs = (__half*)(sm + SM_H);

    const int arow = lane & 15;
    const int asel = (lane >> 4) << 3;
    const int brow = (lane & 7) + ((lane & 16) ? 8 : 0);
    const int bsel = (lane & 8) ? 8 : 0;

    float acc[2][8][4];

    auto zacc = [&]() {
#pragma unroll
        for (int mi = 0; mi < 2; mi++)
#pragma unroll
            for (int ni = 0; ni < 8; ni++)
#pragma unroll
                for (int q = 0; q < 4; q++) acc[mi][ni][q] = 0.0f;
    };

    auto issueA = [&](int ch) {
        const int k0 = ch * 32;
        uint32_t base = smb + (ch & 1) * BUFB;
        int r = tid >> 2, c = (tid & 3) * 8;
        cpa16(base + (uint32_t)(r * PADH + c) * 2, feat + (size_t)(m0 + r) * LDF + k0 + c);
    };
    auto issueB = [&](const __half* W, int ldw, int ch) {
        const int k0 = ch * 32;
        uint32_t base = smb + (ch & 1) * BUFB + ATILE;
#pragma unroll
        for (int i = 0; i < 2; i++) {
            int s = tid + i * 512;
            int r = s >> 2, c = (s & 3) * 8;
            cpa16(base + (uint32_t)(r * PADH + c) * 2, W + (size_t)r * ldw + k0 + c);
        }
    };
    auto compute = [&](uint32_t sA, uint32_t sB) {
#pragma unroll
        for (int ks = 0; ks < 2; ks++) {
            const int kc = ks * 16;
            uint32_t ah[2][4];
#pragma unroll
            for (int mi = 0; mi < 2; mi++)
                ldm4(ah[mi], sA + (uint32_t)((m0w + mi * 16 + arow) * PADH + kc + asel) * 2);
#pragma unroll
            for (int ph = 0; ph < 2; ph++) {
                uint32_t bh[2][4];
#pragma unroll
                for (int pp = 0; pp < 2; pp++) {
                    int p = ph * 2 + pp;
                    ldm4(bh[pp], sB + (uint32_t)((n0w + p * 16 + brow) * PADH + kc + bsel) * 2);
                }
#pragma unroll
                for (int pp = 0; pp < 2; pp++)
#pragma unroll
                    for (int q = 0; q < 2; q++)
#pragma unroll
                        for (int mi = 0; mi < 2; mi++)
                            mma16816(acc[mi][(ph*2+pp)*2+q], ah[mi], bh[pp][q*2], bh[pp][q*2+1]);
            }
        }
    };
    auto epi_smem = [&](const float* bias) {
#pragma unroll
        for (int mi = 0; mi < 2; mi++) {
            int row = m0w + mi * 16 + g;
#pragma unroll
            for (int ni = 0; ni < 8; ni++) {
                int col = n0w + ni * 8 + 2 * t;
                float c0 = bias[col], c1 = bias[col + 1];
                float v0 = fmaxf(acc[mi][ni][0] + c0, 0.f);
                float v1 = fmaxf(acc[mi][ni][1] + c1, 0.f);
                float v2 = fmaxf(acc[mi][ni][2] + c0, 0.f);
                float v3 = fmaxf(acc[mi][ni][3] + c1, 0.f);
                int blk = (col >> 5) * HCHUNK, cc = col & 31;
                *(__half2*)&Hs[blk + row * PADH + cc] =
                    __halves2half2(__float2half_rn(v0), __float2half_rn(v1));
                *(__half2*)&Hs[blk + (row + 8) * PADH + cc] =
                    __halves2half2(__float2half_rn(v2), __float2half_rn(v3));
            }
        }
    };

    // layer 1
    zacc();
    issueA(0); issueB(W1, LDF, 0); CPA_COMMIT();
    for (int ch = 0; ch < 22; ch++) {
        if (ch + 1 < 22) {
            issueA(ch + 1); issueB(W1, LDF, ch + 1); CPA_COMMIT();
            asm volatile("cp.async.wait_group 1;" ::: "memory");
        } else {
            asm volatile("cp.async.wait_group 0;" ::: "memory");
        }
        __syncthreads();
        uint32_t base = smb + (ch & 1) * BUFB;
        compute(base, base + ATILE);
        __syncthreads();
    }
    epi_smem(b1);
    __syncthreads();

    // layer 2
    zacc();
    issueB(W2, 256, 0); CPA_COMMIT();
    for (int ch = 0; ch < 8; ch++) {
        if (ch + 1 < 8) {
            issueB(W2, 256, ch + 1); CPA_COMMIT();
            asm volatile("cp.async.wait_group 1;" ::: "memory");
        } else {
            asm volatile("cp.async.wait_group 0;" ::: "memory");
        }
        __syncthreads();
        compute(sH + (uint32_t)ch * HCHUNK * 2, smb + (ch & 1) * BUFB + ATILE);
        __syncthreads();
    }
    epi_smem(b2);
    __syncthreads();

    // layer 3
    zacc();
    issueB(W3, 256, 0); CPA_COMMIT();
    for (int ch = 0; ch < 8; ch++) {
        if (ch + 1 < 8) {
            issueB(W3, 256, ch + 1); CPA_COMMIT();
            asm volatile("cp.async.wait_group 1;" ::: "memory");
        } else {
            asm volatile("cp.async.wait_group 0;" ::: "memory");
        }
        __syncthreads();
        compute(sH + (uint32_t)ch * HCHUNK * 2, smb + (ch & 1) * BUFB + ATILE);
        __syncthreads();
    }
#pragma unroll
    for (int mi = 0; mi < 2; mi++) {
        int row = m0 + m0w + mi * 16 + g;
#pragma unroll
        for (int ni = 0; ni < 8; ni++) {
            int col = n0w + ni * 8 + 2 * t;
            float c0 = b3[col], c1 = b3[col + 1];
            out[(size_t)row * 283 + col]           = acc[mi][ni][0] + c0;
            out[(size_t)row * 283 + col + 1]       = acc[mi][ni][1] + c1;
            out[(size_t)(row + 8) * 283 + col]     = acc[mi][ni][2] + c0;
            out[(size_t)(row + 8) * 283 + col + 1] = acc[mi][ni][3] + c1;
        }
    }
}

// ---------------- launch -----------------------------------------------------
extern "C" void kernel_launch(void* const* d_in, const int* in_sizes, int n_in,
                              void* d_out, int out_size) {
    const float* pts   = (const float*)d_in[0];
    const float* kp    = (const float*)d_in[1];
    const float* trans = (const float*)d_in[2];
    const int*   nbr   = (const int*)  d_in[3];
    const float* rest  = (const float*)d_in[4];
    const float* lat   = (const float*)d_in[5];
    const float* W1    = (const float*)d_in[6];
    const float* b1    = (const float*)d_in[7];
    const float* W2    = (const float*)d_in[8];
    const float* b2    = (const float*)d_in[9];
    const float* W3    = (const float*)d_in[10];
    const float* b3    = (const float*)d_in[11];
    float*       out   = (float*)d_out;

    void *pFH, *w1h, *w2h, *w3h, *pcnt, *povfn;
    cudaGetSymbolAddress(&pFH,  g_featH);
    cudaGetSymbolAddress(&w1h,  g_W1h);
    cudaGetSymbolAddress(&w2h,  g_W2h);
    cudaGetSymbolAddress(&w3h,  g_W3h);
    cudaGetSymbolAddress(&pcnt, g_ccnt);
    cudaGetSymbolAddress(&povfn, g_ovfn);

    cudaFuncSetAttribute((const void*)mlp_fused,
                         cudaFuncAttributeMaxDynamicSharedMemorySize, MLP_SMEM);

    cudaMemsetAsync(pcnt, 0, (size_t)GRIDC * sizeof(int));
    cudaMemsetAsync(povfn, 0, sizeof(int));
    setup_kernel<<<358, 256>>>(kp, trans, W1, W2, W3,
                               (__half*)w1h, (__half*)w2h, (__half*)w3h);
    knn_query<<<NPTS / 8, 256>>>(pts);
    feat_kernel<<<NPTS / 8, 256>>>(pts, kp, nbr, rest, lat, out);
    mlp_fused<<<NPTS / 128, 512, MLP_SMEM>>>(
        (const __half*)pFH, (const __half*)w1h, (const __half*)w2h,
        (const __half*)w3h, b1, b2, b3, out);
}

// round 14
// speedup vs baseline: 5.2724x; 5.2724x over previous
#include <cuda_runtime.h>
#include <cuda_fp16.h>
#include <cstdint>
#include <math.h>

#define NV      6890
#define NPTS    16384
#define LDF     704

// ---- spatial grid for KNN ----
#define GRIDN   64
#define GRIDC   (GRIDN * GRIDN * GRIDN)
#define GLO     (-5.0f)
#define GH      0.15625f                 // 10/64
#define GINV    6.4f
#define CELLCAP 8
#define OVFCAP  2048

// ---------------- scratch (device globals) -----------------------------------
__device__ __align__(16) __half  g_featH[(size_t)NPTS * LDF];
__device__ __align__(16) __half  g_W1h[(size_t)256 * LDF];
__device__ __align__(16) __half  g_W2h[(size_t)256 * 256];
__device__ __align__(16) __half  g_W3h[(size_t)256 * 256];
__device__ float                 g_Rinv[NV * 9];
__device__ int                   g_knn[NPTS];
__device__ __align__(16) float4  g_cell[(size_t)GRIDC * CELLCAP];
__device__ int                   g_ccnt[GRIDC + 1];   // [GRIDC] = overflow count; memset 0
__device__ __align__(16) float4  g_ovf[OVFCAP];

// ======================= small PTX helpers ===================================
__device__ __forceinline__ uint32_t smem_u32(const void* p) {
    uint32_t a;
    asm("{ .reg .u64 t; cvta.to.shared.u64 t, %1; cvt.u32.u64 %0, t; }" : "=r"(a) : "l"(p));
    return a;
}
__device__ __forceinline__ void cpa16(uint32_t dst, const void* src) {
    asm volatile("cp.async.cg.shared.global [%0], [%1], 16;" :: "r"(dst), "l"(src));
}
#define CPA_COMMIT() asm volatile("cp.async.commit_group;" ::: "memory")

__device__ __forceinline__ void ldm4(uint32_t* r, uint32_t addr) {
    asm volatile("ldmatrix.sync.aligned.m8n8.x4.shared.b16 {%0,%1,%2,%3}, [%4];"
                 : "=r"(r[0]), "=r"(r[1]), "=r"(r[2]), "=r"(r[3]) : "r"(addr));
}
__device__ __forceinline__ void mma16816(float* c, const uint32_t* a, uint32_t b0, uint32_t b1) {
    asm volatile(
        "mma.sync.aligned.m16n8k16.row.col.f32.f16.f16.f32 "
        "{%0,%1,%2,%3}, {%4,%5,%6,%7}, {%8,%9}, {%0,%1,%2,%3};"
        : "+f"(c[0]), "+f"(c[1]), "+f"(c[2]), "+f"(c[3])
        : "r"(a[0]), "r"(a[1]), "r"(a[2]), "r"(a[3]), "r"(b0), "r"(b1));
}

// ---------------- accurate fp32 sincos (no FP64) -----------------------------
__device__ __forceinline__ void sincos_acc(float x, float* s, float* c) {
    const float C1 = 6.28125f;
    const float C2 = (float)1.9353071795864769e-3;
    const float C3 = (float)(6.283185307179586476925286766559 - 6.28125 -
                             (double)((float)1.9353071795864769e-3));
    float q = rintf(x * 0.15915494309189535f);
    float r = fmaf(q, -C1, x);
    r = fmaf(q, -C2, r);
    r = fmaf(q, -C3, r);
    sincosf(r, s, c);
}

// ============ kernel 1: setup (grid build | invert | transpose) ===============
// blocks [0,27): grid build; [27,54): invert; [54,358): weight transpose.
__global__ __launch_bounds__(256) void setup_kernel(
    const float* __restrict__ kp,
    const float* __restrict__ trans,
    const float* __restrict__ W1, const float* __restrict__ W2,
    const float* __restrict__ W3,
    __half* __restrict__ W1h, __half* __restrict__ W2h, __half* __restrict__ W3h)
{
    __shared__ float tile[32][33];
    const int b   = blockIdx.x;
    const int tid = threadIdx.x;

    if (b < 27) {
        int v = b * 256 + tid;
        if (v >= NV) return;
        float kx = kp[v*3], ky = kp[v*3+1], kz = kp[v*3+2];
        int cx = (int)floorf((kx - GLO) * GINV);
        int cy = (int)floorf((ky - GLO) * GINV);
        int cz = (int)floorf((kz - GLO) * GINV);
        float4 rec = make_float4(kx, ky, kz, __int_as_float(v));
        if ((unsigned)cx < GRIDN && (unsigned)cy < GRIDN && (unsigned)cz < GRIDN) {
            int c = (cz * GRIDN + cy) * GRIDN + cx;
            int s = atomicAdd(&g_ccnt[c], 1);
            if (s < CELLCAP) {
                g_cell[(size_t)c * CELLCAP + s] = rec;
            } else {
                int o = atomicAdd(&g_ccnt[GRIDC], 1);
                if (o < OVFCAP) g_ovf[o] = rec;
            }
        } else {
            int o = atomicAdd(&g_ccnt[GRIDC], 1);
            if (o < OVFCAP) g_ovf[o] = rec;
        }

    } else if (b < 54) {
        int v = (b - 27) * 256 + tid;
        if (v >= NV) return;
        float m[16];
#pragma unroll
        for (int k = 0; k < 16; k++) m[k] = trans[k * NV + v];

        float i0  =  m[5]*m[10]*m[15] - m[5]*m[11]*m[14] - m[9]*m[6]*m[15] + m[9]*m[7]*m[14] + m[13]*m[6]*m[11] - m[13]*m[7]*m[10];
        float i4  = -m[4]*m[10]*m[15] + m[4]*m[11]*m[14] + m[8]*m[6]*m[15] - m[8]*m[7]*m[14] - m[12]*m[6]*m[11] + m[12]*m[7]*m[10];
        float i8  =  m[4]*m[9]*m[15]  - m[4]*m[11]*m[13] - m[8]*m[5]*m[15] + m[8]*m[7]*m[13] + m[12]*m[5]*m[11] - m[12]*m[7]*m[9];
        float i12 = -m[4]*m[9]*m[14]  + m[4]*m[10]*m[13] + m[8]*m[5]*m[14] - m[8]*m[6]*m[13] - m[12]*m[5]*m[10] + m[12]*m[6]*m[9];
        float i1  = -m[1]*m[10]*m[15] + m[1]*m[11]*m[14] + m[9]*m[2]*m[15] - m[9]*m[3]*m[14] - m[13]*m[2]*m[11] + m[13]*m[3]*m[10];
        float i5  =  m[0]*m[10]*m[15] - m[0]*m[11]*m[14] - m[8]*m[2]*m[15] + m[8]*m[3]*m[14] + m[12]*m[2]*m[11] - m[12]*m[3]*m[10];
        float i9  = -m[0]*m[9]*m[15]  + m[0]*m[11]*m[13] + m[8]*m[1]*m[15] - m[8]*m[3]*m[13] - m[12]*m[1]*m[11] + m[12]*m[3]*m[9];
        float i2  =  m[1]*m[6]*m[15]  - m[1]*m[7]*m[14]  - m[5]*m[2]*m[15] + m[5]*m[3]*m[14] + m[13]*m[2]*m[7]  - m[13]*m[3]*m[6];
        float i6  = -m[0]*m[6]*m[15]  + m[0]*m[7]*m[14]  + m[4]*m[2]*m[15] - m[4]*m[3]*m[14] - m[12]*m[2]*m[7]  + m[12]*m[3]*m[6];
        float i10 =  m[0]*m[5]*m[15]  - m[0]*m[7]*m[13]  - m[4]*m[1]*m[15] + m[4]*m[3]*m[13] + m[12]*m[1]*m[7]  - m[12]*m[3]*m[5];

        float det = m[0]*i0 + m[1]*i4 + m[2]*i8 + m[3]*i12;
        float id  = 1.0f / det;
        float* R = g_Rinv + v * 9;
        R[0] = i0*id;  R[1] = i1*id;  R[2] = i2*id;
        R[3] = i4*id;  R[4] = i5*id;  R[5] = i6*id;
        R[6] = i8*id;  R[7] = i9*id;  R[8] = i10*id;

    } else {
        int u = b - 54;
        const float* W; __half* Wh; int K, ldk, kb, nb;
        if (u < 176)      { W = W1; Wh = W1h; K = 700; ldk = LDF; kb = (u % 22) * 32; nb = (u / 22) * 32; }
        else if (u < 240) { u -= 176; W = W2; Wh = W2h; K = 256; ldk = 256; kb = (u % 8) * 32; nb = (u / 8) * 32; }
        else              { u -= 240; W = W3; Wh = W3h; K = 256; ldk = 256; kb = (u % 8) * 32; nb = (u / 8) * 32; }

        int tx = tid & 31, ty = tid >> 5;
#pragma unroll
        for (int i = 0; i < 4; i++) {
            int k = kb + ty + i * 8;
            tile[ty + i * 8][tx] = (k < K) ? W[(size_t)k * 256 + nb + tx] : 0.0f;
        }
        __syncthreads();
#pragma unroll
        for (int i = 0; i < 4; i++) {
            int n = nb + ty + i * 8;
            Wh[(size_t)n * ldk + kb + tx] = __float2half_rn(tile[tx][ty + i * 8]);
        }
    }
}

// ============ kernel 2: grid KNN, fixed 125-cell scan + brute fallback ========
__global__ __launch_bounds__(256) void knn_query(const float* __restrict__ pts,
                                                 const float* __restrict__ kp) {
    const int gw   = (blockIdx.x * blockDim.x + threadIdx.x) >> 5;
    const int lane = threadIdx.x & 31;
    if (gw >= NPTS) return;

    const float px = pts[gw*6], py = pts[gw*6+1], pz = pts[gw*6+2];
    int cx = min(max((int)floorf((px - GLO) * GINV), 0), GRIDN - 1);
    int cy = min(max((int)floorf((py - GLO) * GINV), 0), GRIDN - 1);
    int cz = min(max((int)floorf((pz - GLO) * GINV), 0), GRIDN - 1);

    unsigned long long best = ~0ull;   // sentinel d2 bits 0xFFFFFFFF > any valid d2

    // fixed 5x5x5 cube: 4 constant-bound iterations per lane, constant divisors
#pragma unroll
    for (int it = 0; it < 4; it++) {
        int s = lane + it * 32;
        if (s < 125) {
            int x = cx + (s % 5) - 2;
            int y = cy + ((s / 5) % 5) - 2;
            int z = cz + (s / 25) - 2;
            if ((unsigned)x < GRIDN && (unsigned)y < GRIDN && (unsigned)z < GRIDN) {
                int c = (z * GRIDN + y) * GRIDN + x;
                int cnt = min(g_ccnt[c], CELLCAP);
                const float4* cd = &g_cell[(size_t)c * CELLCAP];
                for (int j = 0; j < cnt; j++) {
                    float4 k = cd[j];
                    float dx = px - k.x, dy = py - k.y, dz = pz - k.z;
                    float d2 = fmaf(dx, dx, fmaf(dy, dy, dz * dz));
                    unsigned long long pk =
                        ((unsigned long long)__float_as_uint(d2) << 32) |
                        (unsigned int)__float_as_int(k.w);
                    if (pk < best) best = pk;
                }
            }
        }
    }
    // overflow list (keypoints that spilled the grid)
    {
        int n = min(g_ccnt[GRIDC], OVFCAP);
        for (int i = lane; i < n; i += 32) {
            float4 k = g_ovf[i];
            float dx = px - k.x, dy = py - k.y, dz = pz - k.z;
            float d2 = fmaf(dx, dx, fmaf(dy, dy, dz * dz));
            unsigned long long pk =
                ((unsigned long long)__float_as_uint(d2) << 32) |
                (unsigned int)__float_as_int(k.w);
            if (pk < best) best = pk;
        }
    }
    unsigned long long o;
    o = __shfl_xor_sync(0xffffffffu, best, 1);  if (o < best) best = o;
    o = __shfl_xor_sync(0xffffffffu, best, 2);  if (o < best) best = o;
    o = __shfl_xor_sync(0xffffffffu, best, 4);  if (o < best) best = o;
    o = __shfl_xor_sync(0xffffffffu, best, 8);  if (o < best) best = o;
    o = __shfl_xor_sync(0xffffffffu, best, 16); if (o < best) best = o;

    // exact iff bestd <= 2*GH after radius-2 scan; else brute-force (rare, ~2%)
    const float GUAR = 2.0f * GH;
    if ((uint32_t)(best >> 32) > __float_as_uint(GUAR * GUAR)) {
        for (int i = lane; i < NV; i += 32) {
            float dx = px - kp[i*3], dy = py - kp[i*3+1], dz = pz - kp[i*3+2];
            float d2 = fmaf(dx, dx, fmaf(dy, dy, dz * dz));
            unsigned long long pk =
                ((unsigned long long)__float_as_uint(d2) << 32) | (unsigned int)i;
            if (pk < best) best = pk;
        }
        o = __shfl_xor_sync(0xffffffffu, best, 1);  if (o < best) best = o;
        o = __shfl_xor_sync(0xffffffffu, best, 2);  if (o < best) best = o;
        o = __shfl_xor_sync(0xffffffffu, best, 4);  if (o < best) best = o;
        o = __shfl_xor_sync(0xffffffffu, best, 8);  if (o < best) best = o;
        o = __shfl_xor_sync(0xffffffffu, best, 16); if (o < best) best = o;
    }

    if (lane == 0) g_knn[gw] = (int)(best & 0xFFFFFFFFull);
}

// ---------------- kernel 3: feature build ------------------------------------
__global__ __launch_bounds__(256) void feat_kernel(const float* __restrict__ pts,
                                                   const float* __restrict__ kp,
                                                   const int*   __restrict__ nbr,
                                                   const float* __restrict__ rest,
                                                   const float* __restrict__ lat,
                                                   float*       __restrict__ out) {
    int gw   = (blockIdx.x * blockDim.x + threadIdx.x) >> 5;
    int lane = threadIdx.x & 31;
    if (gw >= NPTS) return;

    int kidx = g_knn[gw];

    float px = pts[gw*6], py = pts[gw*6+1], pz = pts[gw*6+2];

    int vj = (lane < 7) ? nbr[kidx*7 + lane] : 0;
    int j  = (lane < 21) ? (lane / 3) : ((lane < 28) ? (lane - 21) : 0);
    int v  = __shfl_sync(0xffffffffu, vj, j);

    float vf = 0.0f;
    if (lane < 21) {
        vf = rest[v*3 + (lane % 3)];
    } else if (lane < 28) {
        float dx = px - kp[v*3], dy = py - kp[v*3+1], dz = pz - kp[v*3+2];
        vf = sqrtf(dx*dx + dy*dy + dz*dz);
    }

    size_t base = (size_t)gw * LDF;
    if (lane < 28) {
        g_featH[base + lane] = __float2half_rn(vf);
        float s, c;
        sincos_acc(vf, &s, &c);
#pragma unroll
        for (int k = 0; k < 10; k++) {
            g_featH[base + 28  + k*28 + lane] = __float2half_rn(s);
            g_featH[base + 308 + k*28 + lane] = __float2half_rn(c);
            float sn = 2.0f * s * c;
            float cn = fmaf(-2.0f * s, s, 1.0f);
            s = sn; c = cn;
        }
    }
    if (lane < 4) g_featH[base + 700 + lane] = __float2half_rn(0.0f);

#pragma unroll
    for (int it = 0; it < 4; it++) {
        int l  = it * 32 + lane;
        int jj = (l < 112) ? (l >> 4) : 0;
        int vv = __shfl_sync(0xffffffffu, vj, jj);
        if (l < 112) g_featH[base + 588 + l] = __float2half_rn(lat[vv*16 + (l & 15)]);
    }

    if (lane == 0) {
        float dx = px - kp[kidx*3], dy = py - kp[kidx*3+1], dz = pz - kp[kidx*3+2];
        const float* R = g_Rinv + kidx * 9;
        float d0 = R[0]*dx + R[1]*dy + R[2]*dz;
        float d1 = R[3]*dx + R[4]*dy + R[5]*dz;
        float d2 = R[6]*dx + R[7]*dy + R[8]*dz;
        float nn = sqrtf(d0*d0 + d1*d1 + d2*d2);
        float iv = 1.0f / fmaxf(nn, 1e-12f);
        d0 *= iv; d1 *= iv; d2 *= iv;
        float* op = out + (size_t)gw * 283 + 256;
        op[0] = d0; op[1] = d1; op[2] = d2;
        float dir[3] = {d0, d1, d2};
#pragma unroll
        for (int c = 0; c < 3; c++) {
            float s, cc;
            sincos_acc(dir[c], &s, &cc);
#pragma unroll
            for (int k = 0; k < 4; k++) {
                op[3  + k*3 + c] = s;
                op[15 + k*3 + c] = cc;
                float sn = 2.0f * s * cc;
                float cn = fmaf(-2.0f * s, s, 1.0f);
                s = sn; cc = cn;
            }
        }
    }
}

// ---------------- kernel 4: fused 3-layer MLP (fp16 HMMA) --------------------
#define PADH    40
#define ATILE   (128 * PADH * 2)
#define BTILE   (256 * PADH * 2)
#define BUFB    (ATILE + BTILE)
#define SM_H    (2 * BUFB)
#define HCHUNK  (128 * PADH)
#define MLP_SMEM (SM_H + 8 * HCHUNK * 2)   // 143360 B

__global__ __launch_bounds__(512, 1) void mlp_fused(
    const __half* __restrict__ feat,
    const __half* __restrict__ W1, const __half* __restrict__ W2,
    const __half* __restrict__ W3,
    const float* __restrict__ b1, const float* __restrict__ b2,
    const float* __restrict__ b3,
    float* __restrict__ out)
{
    extern __shared__ char sm[];
    const int tid  = threadIdx.x;
    const int wid  = tid >> 5, lane = tid & 31;
    const int g    = lane >> 2, t = lane & 3;
    const int m0   = blockIdx.x * 128;
    const int m0w  = (wid >> 2) * 32, n0w = (wid & 3) * 64;
    const uint32_t smb = smem_u32(sm);
    const uint32_t sH  = smb + SM_H;
    __half* Hs = (__half*)(sm + SM_H);

    const int arow = lane & 15;
    const int asel = (lane >> 4) << 3;
    const int brow = (lane & 7) + ((lane & 16) ? 8 : 0);
    const int bsel = (lane & 8) ? 8 : 0;

    float acc[2][8][4];

    auto zacc = [&]() {
#pragma unroll
        for (int mi = 0; mi < 2; mi++)
#pragma unroll
            for (int ni = 0; ni < 8; ni++)
#pragma unroll
                for (int q = 0; q < 4; q++) acc[mi][ni][q] = 0.0f;
    };

    auto issueA = [&](int ch) {
        const int k0 = ch * 32;
        uint32_t base = smb + (ch & 1) * BUFB;
        int r = tid >> 2, c = (tid & 3) * 8;
        cpa16(base + (uint32_t)(r * PADH + c) * 2, feat + (size_t)(m0 + r) * LDF + k0 + c);
    };
    auto issueB = [&](const __half* W, int ldw, int ch) {
        const int k0 = ch * 32;
        uint32_t base = smb + (ch & 1) * BUFB + ATILE;
#pragma unroll
        for (int i = 0; i < 2; i++) {
            int s = tid + i * 512;
            int r = s >> 2, c = (s & 3) * 8;
            cpa16(base + (uint32_t)(r * PADH + c) * 2, W + (size_t)r * ldw + k0 + c);
        }
    };
    auto compute = [&](uint32_t sA, uint32_t sB) {
#pragma unroll
        for (int ks = 0; ks < 2; ks++) {
            const int kc = ks * 16;
            uint32_t ah[2][4];
#pragma unroll
            for (int mi = 0; mi < 2; mi++)
                ldm4(ah[mi], sA + (uint32_t)((m0w + mi * 16 + arow) * PADH + kc + asel) * 2);
#pragma unroll
            for (int ph = 0; ph < 2; ph++) {
                uint32_t bh[2][4];
#pragma unroll
                for (int pp = 0; pp < 2; pp++) {
                    int p = ph * 2 + pp;
                    ldm4(bh[pp], sB + (uint32_t)((n0w + p * 16 + brow) * PADH + kc + bsel) * 2);
                }
#pragma unroll
                for (int pp = 0; pp < 2; pp++)
#pragma unroll
                    for (int q = 0; q < 2; q++)
#pragma unroll
                        for (int mi = 0; mi < 2; mi++)
                            mma16816(acc[mi][(ph*2+pp)*2+q], ah[mi], bh[pp][q*2], bh[pp][q*2+1]);
            }
        }
    };
    auto epi_smem = [&](const float* bias) {
#pragma unroll
        for (int mi = 0; mi < 2; mi++) {
            int row = m0w + mi * 16 + g;
#pragma unroll
            for (int ni = 0; ni < 8; ni++) {
                int col = n0w + ni * 8 + 2 * t;
                float c0 = bias[col], c1 = bias[col + 1];
                float v0 = fmaxf(acc[mi][ni][0] + c0, 0.f);
                float v1 = fmaxf(acc[mi][ni][1] + c1, 0.f);
                float v2 = fmaxf(acc[mi][ni][2] + c0, 0.f);
                float v3 = fmaxf(acc[mi][ni][3] + c1, 0.f);
                int blk = (col >> 5) * HCHUNK, cc = col & 31;
                *(__half2*)&Hs[blk + row * PADH + cc] =
                    __halves2half2(__float2half_rn(v0), __float2half_rn(v1));
                *(__half2*)&Hs[blk + (row + 8) * PADH + cc] =
                    __halves2half2(__float2half_rn(v2), __float2half_rn(v3));
            }
        }
    };

    // layer 1
    zacc();
    issueA(0); issueB(W1, LDF, 0); CPA_COMMIT();
    for (int ch = 0; ch < 22; ch++) {
        if (ch + 1 < 22) {
            issueA(ch + 1); issueB(W1, LDF, ch + 1); CPA_COMMIT();
            asm volatile("cp.async.wait_group 1;" ::: "memory");
        } else {
            asm volatile("cp.async.wait_group 0;" ::: "memory");
        }
        __syncthreads();
        uint32_t base = smb + (ch & 1) * BUFB;
        compute(base, base + ATILE);
        __syncthreads();
    }
    epi_smem(b1);
    __syncthreads();

    // layer 2
    zacc();
    issueB(W2, 256, 0); CPA_COMMIT();
    for (int ch = 0; ch < 8; ch++) {
        if (ch + 1 < 8) {
            issueB(W2, 256, ch + 1); CPA_COMMIT();
            asm volatile("cp.async.wait_group 1;" ::: "memory");
        } else {
            asm volatile("cp.async.wait_group 0;" ::: "memory");
        }
        __syncthreads();
        compute(sH + (uint32_t)ch * HCHUNK * 2, smb + (ch & 1) * BUFB + ATILE);
        __syncthreads();
    }
    epi_smem(b2);
    __syncthreads();

    // layer 3
    zacc();
    issueB(W3, 256, 0); CPA_COMMIT();
    for (int ch = 0; ch < 8; ch++) {
        if (ch + 1 < 8) {
            issueB(W3, 256, ch + 1); CPA_COMMIT();
            asm volatile("cp.async.wait_group 1;" ::: "memory");
        } else {
            asm volatile("cp.async.wait_group 0;" ::: "memory");
        }
        __syncthreads();
        compute(sH + (uint32_t)ch * HCHUNK * 2, smb + (ch & 1) * BUFB + ATILE);
        __syncthreads();
    }
#pragma unroll
    for (int mi = 0; mi < 2; mi++) {
        int row = m0 + m0w + mi * 16 + g;
#pragma unroll
        for (int ni = 0; ni < 8; ni++) {
            int col = n0w + ni * 8 + 2 * t;
            float c0 = b3[col], c1 = b3[col + 1];
            out[(size_t)row * 283 + col]           = acc[mi][ni][0] + c0;
            out[(size_t)row * 283 + col + 1]       = acc[mi][ni][1] + c1;
            out[(size_t)(row + 8) * 283 + col]     = acc[mi][ni][2] + c0;
            out[(size_t)(row + 8) * 283 + col + 1] = acc[mi][ni][3] + c1;
        }
    }
}

// ---------------- launch -----------------------------------------------------
extern "C" void kernel_launch(void* const* d_in, const int* in_sizes, int n_in,
                              void* d_out, int out_size) {
    const float* pts   = (const float*)d_in[0];
    const float* kp    = (const float*)d_in[1];
    const float* trans = (const float*)d_in[2];
    const int*   nbr   = (const int*)  d_in[3];
    const float* rest  = (const float*)d_in[4];
    const float* lat   = (const float*)d_in[5];
    const float* W1    = (const float*)d_in[6];
    const float* b1    = (const float*)d_in[7];
    const float* W2    = (const float*)d_in[8];
    const float* b2    = (const float*)d_in[9];
    const float* W3    = (const float*)d_in[10];
    const float* b3    = (const float*)d_in[11];
    float*       out   = (float*)d_out;

    void *pFH, *w1h, *w2h, *w3h, *pcnt;
    cudaGetSymbolAddress(&pFH,  g_featH);
    cudaGetSymbolAddress(&w1h,  g_W1h);
    cudaGetSymbolAddress(&w2h,  g_W2h);
    cudaGetSymbolAddress(&w3h,  g_W3h);
    cudaGetSymbolAddress(&pcnt, g_ccnt);

    cudaFuncSetAttribute((const void*)mlp_fused,
                         cudaFuncAttributeMaxDynamicSharedMemorySize, MLP_SMEM);

    cudaMemsetAsync(pcnt, 0, (size_t)(GRIDC + 1) * sizeof(int));
    setup_kernel<<<358, 256>>>(kp, trans, W1, W2, W3,
                               (__half*)w1h, (__half*)w2h, (__half*)w3h);
    knn_query<<<NPTS / 8, 256>>>(pts, kp);
    feat_kernel<<<NPTS / 8, 256>>>(pts, kp, nbr, rest, lat, out);
    mlp_fused<<<NPTS / 128, 512, MLP_SMEM>>>(
        (const __half*)pFH, (const __half*)w1h, (const __half*)w2h,
        (const __half*)w3h, b1, b2, b3, out);
}

// round 15
// speedup vs baseline: 5.4227x; 1.0285x over previous
#include <cuda_runtime.h>
#include <cuda_fp16.h>
#include <cstdint>
#include <math.h>

#define NV      6890
#define NPTS    16384
#define LDF     704

// ---- spatial grid for KNN ----
#define GRIDN   64
#define GRIDC   (GRIDN * GRIDN * GRIDN)
#define GLO     (-5.0f)
#define GH      0.15625f
#define GINV    6.4f
#define CELLCAP 8
#define OVFCAP  2048

// ---------------- scratch (device globals) -----------------------------------
__device__ __align__(16) __half  g_featH[(size_t)NPTS * LDF];
__device__ __align__(16) __half  g_W1h[(size_t)256 * LDF];
__device__ __align__(16) __half  g_W2h[(size_t)256 * 256];
__device__ __align__(16) __half  g_W3h[(size_t)256 * 256];
__device__ float                 g_Rinv[NV * 9];
__device__ int                   g_knn[NPTS];
__device__ __align__(16) float4  g_cell[(size_t)GRIDC * CELLCAP];
__device__ int                   g_ccnt[GRIDC + 1];   // [GRIDC] = overflow count; memset 0
__device__ __align__(16) float4  g_ovf[OVFCAP];

// ======================= small PTX helpers ===================================
__device__ __forceinline__ uint32_t smem_u32(const void* p) {
    uint32_t a;
    asm("{ .reg .u64 t; cvta.to.shared.u64 t, %1; cvt.u32.u64 %0, t; }" : "=r"(a) : "l"(p));
    return a;
}
__device__ __forceinline__ void cpa16(uint32_t dst, const void* src) {
    asm volatile("cp.async.cg.shared.global [%0], [%1], 16;" :: "r"(dst), "l"(src));
}
#define CPA_COMMIT() asm volatile("cp.async.commit_group;" ::: "memory")

__device__ __forceinline__ void ldm4(uint32_t* r, uint32_t addr) {
    asm volatile("ldmatrix.sync.aligned.m8n8.x4.shared.b16 {%0,%1,%2,%3}, [%4];"
                 : "=r"(r[0]), "=r"(r[1]), "=r"(r[2]), "=r"(r[3]) : "r"(addr));
}
__device__ __forceinline__ void mma16816(float* c, const uint32_t* a, uint32_t b0, uint32_t b1) {
    asm volatile(
        "mma.sync.aligned.m16n8k16.row.col.f32.f16.f16.f32 "
        "{%0,%1,%2,%3}, {%4,%5,%6,%7}, {%8,%9}, {%0,%1,%2,%3};"
        : "+f"(c[0]), "+f"(c[1]), "+f"(c[2]), "+f"(c[3])
        : "r"(a[0]), "r"(a[1]), "r"(a[2]), "r"(a[3]), "r"(b0), "r"(b1));
}

// ---------------- accurate fp32 sincos (no FP64) -----------------------------
__device__ __forceinline__ void sincos_acc(float x, float* s, float* c) {
    const float C1 = 6.28125f;
    const float C2 = (float)1.9353071795864769e-3;
    const float C3 = (float)(6.283185307179586476925286766559 - 6.28125 -
                             (double)((float)1.9353071795864769e-3));
    float q = rintf(x * 0.15915494309189535f);
    float r = fmaf(q, -C1, x);
    r = fmaf(q, -C2, r);
    r = fmaf(q, -C3, r);
    sincosf(r, s, c);
}

// ============ kernel 1: setup (grid build | invert | transpose) ===============
__global__ __launch_bounds__(256) void setup_kernel(
    const float* __restrict__ kp,
    const float* __restrict__ trans,
    const float* __restrict__ W1, const float* __restrict__ W2,
    const float* __restrict__ W3,
    __half* __restrict__ W1h, __half* __restrict__ W2h, __half* __restrict__ W3h)
{
    __shared__ float tile[32][33];
    const int b   = blockIdx.x;
    const int tid = threadIdx.x;

    if (b < 27) {
        int v = b * 256 + tid;
        if (v >= NV) return;
        float kx = kp[v*3], ky = kp[v*3+1], kz = kp[v*3+2];
        int cx = (int)floorf((kx - GLO) * GINV);
        int cy = (int)floorf((ky - GLO) * GINV);
        int cz = (int)floorf((kz - GLO) * GINV);
        float4 rec = make_float4(kx, ky, kz, __int_as_float(v));
        if ((unsigned)cx < GRIDN && (unsigned)cy < GRIDN && (unsigned)cz < GRIDN) {
            int c = (cz * GRIDN + cy) * GRIDN + cx;
            int s = atomicAdd(&g_ccnt[c], 1);
            if (s < CELLCAP) {
                g_cell[(size_t)c * CELLCAP + s] = rec;
            } else {
                int o = atomicAdd(&g_ccnt[GRIDC], 1);
                if (o < OVFCAP) g_ovf[o] = rec;
            }
        } else {
            int o = atomicAdd(&g_ccnt[GRIDC], 1);
            if (o < OVFCAP) g_ovf[o] = rec;
        }

    } else if (b < 54) {
        int v = (b - 27) * 256 + tid;
        if (v >= NV) return;
        float m[16];
#pragma unroll
        for (int k = 0; k < 16; k++) m[k] = trans[k * NV + v];

        float i0  =  m[5]*m[10]*m[15] - m[5]*m[11]*m[14] - m[9]*m[6]*m[15] + m[9]*m[7]*m[14] + m[13]*m[6]*m[11] - m[13]*m[7]*m[10];
        float i4  = -m[4]*m[10]*m[15] + m[4]*m[11]*m[14] + m[8]*m[6]*m[15] - m[8]*m[7]*m[14] - m[12]*m[6]*m[11] + m[12]*m[7]*m[10];
        float i8  =  m[4]*m[9]*m[15]  - m[4]*m[11]*m[13] - m[8]*m[5]*m[15] + m[8]*m[7]*m[13] + m[12]*m[5]*m[11] - m[12]*m[7]*m[9];
        float i12 = -m[4]*m[9]*m[14]  + m[4]*m[10]*m[13] + m[8]*m[5]*m[14] - m[8]*m[6]*m[13] - m[12]*m[5]*m[10] + m[12]*m[6]*m[9];
        float i1  = -m[1]*m[10]*m[15] + m[1]*m[11]*m[14] + m[9]*m[2]*m[15] - m[9]*m[3]*m[14] - m[13]*m[2]*m[11] + m[13]*m[3]*m[10];
        float i5  =  m[0]*m[10]*m[15] - m[0]*m[11]*m[14] - m[8]*m[2]*m[15] + m[8]*m[3]*m[14] + m[12]*m[2]*m[11] - m[12]*m[3]*m[10];
        float i9  = -m[0]*m[9]*m[15]  + m[0]*m[11]*m[13] + m[8]*m[1]*m[15] - m[8]*m[3]*m[13] - m[12]*m[1]*m[11] + m[12]*m[3]*m[9];
        float i2  =  m[1]*m[6]*m[15]  - m[1]*m[7]*m[14]  - m[5]*m[2]*m[15] + m[5]*m[3]*m[14] + m[13]*m[2]*m[7]  - m[13]*m[3]*m[6];
        float i6  = -m[0]*m[6]*m[15]  + m[0]*m[7]*m[14]  + m[4]*m[2]*m[15] - m[4]*m[3]*m[14] - m[12]*m[2]*m[7]  + m[12]*m[3]*m[6];
        float i10 =  m[0]*m[5]*m[15]  - m[0]*m[7]*m[13]  - m[4]*m[1]*m[15] + m[4]*m[3]*m[13] + m[12]*m[1]*m[7]  - m[12]*m[3]*m[5];

        float det = m[0]*i0 + m[1]*i4 + m[2]*i8 + m[3]*i12;
        float id  = 1.0f / det;
        float* R = g_Rinv + v * 9;
        R[0] = i0*id;  R[1] = i1*id;  R[2] = i2*id;
        R[3] = i4*id;  R[4] = i5*id;  R[5] = i6*id;
        R[6] = i8*id;  R[7] = i9*id;  R[8] = i10*id;

    } else {
        int u = b - 54;
        const float* W; __half* Wh; int K, ldk, kb, nb;
        if (u < 176)      { W = W1; Wh = W1h; K = 700; ldk = LDF; kb = (u % 22) * 32; nb = (u / 22) * 32; }
        else if (u < 240) { u -= 176; W = W2; Wh = W2h; K = 256; ldk = 256; kb = (u % 8) * 32; nb = (u / 8) * 32; }
        else              { u -= 240; W = W3; Wh = W3h; K = 256; ldk = 256; kb = (u % 8) * 32; nb = (u / 8) * 32; }

        int tx = tid & 31, ty = tid >> 5;
#pragma unroll
        for (int i = 0; i < 4; i++) {
            int k = kb + ty + i * 8;
            tile[ty + i * 8][tx] = (k < K) ? W[(size_t)k * 256 + nb + tx] : 0.0f;
        }
        __syncthreads();
#pragma unroll
        for (int i = 0; i < 4; i++) {
            int n = nb + ty + i * 8;
            Wh[(size_t)n * ldk + kb + tx] = __float2half_rn(tile[tx][ty + i * 8]);
        }
    }
}

// ============ kernel 2: grid KNN, fixed 125-cell scan + brute fallback ========
__global__ __launch_bounds__(256) void knn_query(const float* __restrict__ pts,
                                                 const float* __restrict__ kp) {
    const int gw   = (blockIdx.x * blockDim.x + threadIdx.x) >> 5;
    const int lane = threadIdx.x & 31;
    if (gw >= NPTS) return;

    const float px = pts[gw*6], py = pts[gw*6+1], pz = pts[gw*6+2];
    int cx = min(max((int)floorf((px - GLO) * GINV), 0), GRIDN - 1);
    int cy = min(max((int)floorf((py - GLO) * GINV), 0), GRIDN - 1);
    int cz = min(max((int)floorf((pz - GLO) * GINV), 0), GRIDN - 1);

    unsigned long long best = ~0ull;

#pragma unroll
    for (int it = 0; it < 4; it++) {
        int s = lane + it * 32;
        if (s < 125) {
            int x = cx + (s % 5) - 2;
            int y = cy + ((s / 5) % 5) - 2;
            int z = cz + (s / 25) - 2;
            if ((unsigned)x < GRIDN && (unsigned)y < GRIDN && (unsigned)z < GRIDN) {
                int c = (z * GRIDN + y) * GRIDN + x;
                int cnt = min(g_ccnt[c], CELLCAP);
                const float4* cd = &g_cell[(size_t)c * CELLCAP];
                for (int j = 0; j < cnt; j++) {
                    float4 k = cd[j];
                    float dx = px - k.x, dy = py - k.y, dz = pz - k.z;
                    float d2 = fmaf(dx, dx, fmaf(dy, dy, dz * dz));
                    unsigned long long pk =
                        ((unsigned long long)__float_as_uint(d2) << 32) |
                        (unsigned int)__float_as_int(k.w);
                    if (pk < best) best = pk;
                }
            }
        }
    }
    {
        int n = min(g_ccnt[GRIDC], OVFCAP);
        for (int i = lane; i < n; i += 32) {
            float4 k = g_ovf[i];
            float dx = px - k.x, dy = py - k.y, dz = pz - k.z;
            float d2 = fmaf(dx, dx, fmaf(dy, dy, dz * dz));
            unsigned long long pk =
                ((unsigned long long)__float_as_uint(d2) << 32) |
                (unsigned int)__float_as_int(k.w);
            if (pk < best) best = pk;
        }
    }
    unsigned long long o;
    o = __shfl_xor_sync(0xffffffffu, best, 1);  if (o < best) best = o;
    o = __shfl_xor_sync(0xffffffffu, best, 2);  if (o < best) best = o;
    o = __shfl_xor_sync(0xffffffffu, best, 4);  if (o < best) best = o;
    o = __shfl_xor_sync(0xffffffffu, best, 8);  if (o < best) best = o;
    o = __shfl_xor_sync(0xffffffffu, best, 16); if (o < best) best = o;

    const float GUAR = 2.0f * GH;
    if ((uint32_t)(best >> 32) > __float_as_uint(GUAR * GUAR)) {
        for (int i = lane; i < NV; i += 32) {
            float dx = px - kp[i*3], dy = py - kp[i*3+1], dz = pz - kp[i*3+2];
            float d2 = fmaf(dx, dx, fmaf(dy, dy, dz * dz));
            unsigned long long pk =
                ((unsigned long long)__float_as_uint(d2) << 32) | (unsigned int)i;
            if (pk < best) best = pk;
        }
        o = __shfl_xor_sync(0xffffffffu, best, 1);  if (o < best) best = o;
        o = __shfl_xor_sync(0xffffffffu, best, 2);  if (o < best) best = o;
        o = __shfl_xor_sync(0xffffffffu, best, 4);  if (o < best) best = o;
        o = __shfl_xor_sync(0xffffffffu, best, 8);  if (o < best) best = o;
        o = __shfl_xor_sync(0xffffffffu, best, 16); if (o < best) best = o;
    }

    if (lane == 0) g_knn[gw] = (int)(best & 0xFFFFFFFFull);
}

// ---------------- kernel 3: feature build ------------------------------------
__global__ __launch_bounds__(256) void feat_kernel(const float* __restrict__ pts,
                                                   const float* __restrict__ kp,
                                                   const int*   __restrict__ nbr,
                                                   const float* __restrict__ rest,
                                                   const float* __restrict__ lat,
                                                   float*       __restrict__ out) {
    int gw   = (blockIdx.x * blockDim.x + threadIdx.x) >> 5;
    int lane = threadIdx.x & 31;
    if (gw >= NPTS) return;

    int kidx = g_knn[gw];

    float px = pts[gw*6], py = pts[gw*6+1], pz = pts[gw*6+2];

    int vj = (lane < 7) ? nbr[kidx*7 + lane] : 0;
    int j  = (lane < 21) ? (lane / 3) : ((lane < 28) ? (lane - 21) : 0);
    int v  = __shfl_sync(0xffffffffu, vj, j);

    float vf = 0.0f;
    if (lane < 21) {
        vf = rest[v*3 + (lane % 3)];
    } else if (lane < 28) {
        float dx = px - kp[v*3], dy = py - kp[v*3+1], dz = pz - kp[v*3+2];
        vf = sqrtf(dx*dx + dy*dy + dz*dz);
    }

    size_t base = (size_t)gw * LDF;
    if (lane < 28) {
        g_featH[base + lane] = __float2half_rn(vf);
        float s, c;
        sincos_acc(vf, &s, &c);
#pragma unroll
        for (int k = 0; k < 10; k++) {
            g_featH[base + 28  + k*28 + lane] = __float2half_rn(s);
            g_featH[base + 308 + k*28 + lane] = __float2half_rn(c);
            float sn = 2.0f * s * c;
            float cn = fmaf(-2.0f * s, s, 1.0f);
            s = sn; c = cn;
        }
    }
    if (lane < 4) g_featH[base + 700 + lane] = __float2half_rn(0.0f);

#pragma unroll
    for (int it = 0; it < 4; it++) {
        int l  = it * 32 + lane;
        int jj = (l < 112) ? (l >> 4) : 0;
        int vv = __shfl_sync(0xffffffffu, vj, jj);
        if (l < 112) g_featH[base + 588 + l] = __float2half_rn(lat[vv*16 + (l & 15)]);
    }

    if (lane == 0) {
        float dx = px - kp[kidx*3], dy = py - kp[kidx*3+1], dz = pz - kp[kidx*3+2];
        const float* R = g_Rinv + kidx * 9;
        float d0 = R[0]*dx + R[1]*dy + R[2]*dz;
        float d1 = R[3]*dx + R[4]*dy + R[5]*dz;
        float d2 = R[6]*dx + R[7]*dy + R[8]*dz;
        float nn = sqrtf(d0*d0 + d1*d1 + d2*d2);
        float iv = 1.0f / fmaxf(nn, 1e-12f);
        d0 *= iv; d1 *= iv; d2 *= iv;
        float* op = out + (size_t)gw * 283 + 256;
        op[0] = d0; op[1] = d1; op[2] = d2;
        float dir[3] = {d0, d1, d2};
#pragma unroll
        for (int c = 0; c < 3; c++) {
            float s, cc;
            sincos_acc(dir[c], &s, &cc);
#pragma unroll
            for (int k = 0; k < 4; k++) {
                op[3  + k*3 + c] = s;
                op[15 + k*3 + c] = cc;
                float sn = 2.0f * s * cc;
                float cn = fmaf(-2.0f * s, s, 1.0f);
                s = sn; cc = cn;
            }
        }
    }
}

// ---------------- kernel 4: fused 3-layer MLP, 64-row CTA, 2 CTAs/SM ---------
#define PADH    40
#define MROWS   64
#define ATILE   (MROWS * PADH * 2)         // 5120 B
#define BTILE   (256 * PADH * 2)           // 20480 B
#define BUFB    (ATILE + BTILE)            // 25600 B
#define SM_H    (2 * BUFB)                 // 51200
#define HCHUNK  (MROWS * PADH)             // halves per 32-K chunk block
#define MLP_SMEM (SM_H + 8 * HCHUNK * 2)   // 51200 + 40960 = 92160 B

__global__ __launch_bounds__(256, 2) void mlp_fused(
    const __half* __restrict__ feat,
    const __half* __restrict__ W1, const __half* __restrict__ W2,
    const __half* __restrict__ W3,
    const float* __restrict__ b1, const float* __restrict__ b2,
    const float* __restrict__ b3,
    float* __restrict__ out)
{
    extern __shared__ char sm[];
    const int tid  = threadIdx.x;
    const int wid  = tid >> 5, lane = tid & 31;
    const int g    = lane >> 2, t = lane & 3;
    const int m0   = blockIdx.x * MROWS;
    const int m0w  = (wid >> 2) * 32, n0w = (wid & 3) * 64;   // 2 M-warps x 4 N-warps
    const uint32_t smb = smem_u32(sm);
    const uint32_t sH  = smb + SM_H;
    __half* Hs = (__half*)(sm + SM_H);

    const int arow = lane & 15;
    const int asel = (lane >> 4) << 3;
    const int brow = (lane & 7) + ((lane & 16) ? 8 : 0);
    const int bsel = (lane & 8) ? 8 : 0;

    float acc[2][8][4];

    auto zacc = [&]() {
#pragma unroll
        for (int mi = 0; mi < 2; mi++)
#pragma unroll
            for (int ni = 0; ni < 8; ni++)
#pragma unroll
                for (int q = 0; q < 4; q++) acc[mi][ni][q] = 0.0f;
    };

    auto issueA = [&](int ch) {                 // 256 segs: one per thread
        const int k0 = ch * 32;
        uint32_t base = smb + (ch & 1) * BUFB;
        int r = tid >> 2, c = (tid & 3) * 8;
        cpa16(base + (uint32_t)(r * PADH + c) * 2, feat + (size_t)(m0 + r) * LDF + k0 + c);
    };
    auto issueB = [&](const __half* W, int ldw, int ch) {   // 1024 segs: 4 per thread
        const int k0 = ch * 32;
        uint32_t base = smb + (ch & 1) * BUFB + ATILE;
#pragma unroll
        for (int i = 0; i < 4; i++) {
            int s = tid + i * 256;
            int r = s >> 2, c = (s & 3) * 8;
            cpa16(base + (uint32_t)(r * PADH + c) * 2, W + (size_t)r * ldw + k0 + c);
        }
    };
    auto compute = [&](uint32_t sA, uint32_t sB) {
#pragma unroll
        for (int ks = 0; ks < 2; ks++) {
            const int kc = ks * 16;
            uint32_t ah[2][4];
#pragma unroll
            for (int mi = 0; mi < 2; mi++)
                ldm4(ah[mi], sA + (uint32_t)((m0w + mi * 16 + arow) * PADH + kc + asel) * 2);
#pragma unroll
            for (int ph = 0; ph < 2; ph++) {
                uint32_t bh[2][4];
#pragma unroll
                for (int pp = 0; pp < 2; pp++) {
                    int p = ph * 2 + pp;
                    ldm4(bh[pp], sB + (uint32_t)((n0w + p * 16 + brow) * PADH + kc + bsel) * 2);
                }
#pragma unroll
                for (int pp = 0; pp < 2; pp++)
#pragma unroll
                    for (int q = 0; q < 2; q++)
#pragma unroll
                        for (int mi = 0; mi < 2; mi++)
                            mma16816(acc[mi][(ph*2+pp)*2+q], ah[mi], bh[pp][q*2], bh[pp][q*2+1]);
            }
        }
    };
    auto epi_smem = [&](const float* bias) {
#pragma unroll
        for (int mi = 0; mi < 2; mi++) {
            int row = m0w + mi * 16 + g;
#pragma unroll
            for (int ni = 0; ni < 8; ni++) {
                int col = n0w + ni * 8 + 2 * t;
                float c0 = bias[col], c1 = bias[col + 1];
                float v0 = fmaxf(acc[mi][ni][0] + c0, 0.f);
                float v1 = fmaxf(acc[mi][ni][1] + c1, 0.f);
                float v2 = fmaxf(acc[mi][ni][2] + c0, 0.f);
                float v3 = fmaxf(acc[mi][ni][3] + c1, 0.f);
                int blk = (col >> 5) * HCHUNK, cc = col & 31;
                *(__half2*)&Hs[blk + row * PADH + cc] =
                    __halves2half2(__float2half_rn(v0), __float2half_rn(v1));
                *(__half2*)&Hs[blk + (row + 8) * PADH + cc] =
                    __halves2half2(__float2half_rn(v2), __float2half_rn(v3));
            }
        }
    };

    // layer 1: feat(704) -> h1
    zacc();
    issueA(0); issueB(W1, LDF, 0); CPA_COMMIT();
    for (int ch = 0; ch < 22; ch++) {
        if (ch + 1 < 22) {
            issueA(ch + 1); issueB(W1, LDF, ch + 1); CPA_COMMIT();
            asm volatile("cp.async.wait_group 1;" ::: "memory");
        } else {
            asm volatile("cp.async.wait_group 0;" ::: "memory");
        }
        __syncthreads();
        uint32_t base = smb + (ch & 1) * BUFB;
        compute(base, base + ATILE);
        __syncthreads();
    }
    epi_smem(b1);
    __syncthreads();

    // layer 2: h1 -> h2 (in place)
    zacc();
    issueB(W2, 256, 0); CPA_COMMIT();
    for (int ch = 0; ch < 8; ch++) {
        if (ch + 1 < 8) {
            issueB(W2, 256, ch + 1); CPA_COMMIT();
            asm volatile("cp.async.wait_group 1;" ::: "memory");
        } else {
            asm volatile("cp.async.wait_group 0;" ::: "memory");
        }
        __syncthreads();
        compute(sH + (uint32_t)ch * HCHUNK * 2, smb + (ch & 1) * BUFB + ATILE);
        __syncthreads();
    }
    epi_smem(b2);
    __syncthreads();

    // layer 3: h2 -> out
    zacc();
    issueB(W3, 256, 0); CPA_COMMIT();
    for (int ch = 0; ch < 8; ch++) {
        if (ch + 1 < 8) {
            issueB(W3, 256, ch + 1); CPA_COMMIT();
            asm volatile("cp.async.wait_group 1;" ::: "memory");
        } else {
            asm volatile("cp.async.wait_group 0;" ::: "memory");
        }
        __syncthreads();
        compute(sH + (uint32_t)ch * HCHUNK * 2, smb + (ch & 1) * BUFB + ATILE);
        __syncthreads();
    }
#pragma unroll
    for (int mi = 0; mi < 2; mi++) {
        int row = m0 + m0w + mi * 16 + g;
#pragma unroll
        for (int ni = 0; ni < 8; ni++) {
            int col = n0w + ni * 8 + 2 * t;
            float c0 = b3[col], c1 = b3[col + 1];
            out[(size_t)row * 283 + col]           = acc[mi][ni][0] + c0;
            out[(size_t)row * 283 + col + 1]       = acc[mi][ni][1] + c1;
            out[(size_t)(row + 8) * 283 + col]     = acc[mi][ni][2] + c0;
            out[(size_t)(row + 8) * 283 + col + 1] = acc[mi][ni][3] + c1;
        }
    }
}

// ---------------- launch -----------------------------------------------------
extern "C" void kernel_launch(void* const* d_in, const int* in_sizes, int n_in,
                              void* d_out, int out_size) {
    const float* pts   = (const float*)d_in[0];
    const float* kp    = (const float*)d_in[1];
    const float* trans = (const float*)d_in[2];
    const int*   nbr   = (const int*)  d_in[3];
    const float* rest  = (const float*)d_in[4];
    const float* lat   = (const float*)d_in[5];
    const float* W1    = (const float*)d_in[6];
    const float* b1    = (const float*)d_in[7];
    const float* W2    = (const float*)d_in[8];
    const float* b2    = (const float*)d_in[9];
    const float* W3    = (const float*)d_in[10];
    const float* b3    = (const float*)d_in[11];
    float*       out   = (float*)d_out;

    void *pFH, *w1h, *w2h, *w3h, *pcnt;
    cudaGetSymbolAddress(&pFH,  g_featH);
    cudaGetSymbolAddress(&w1h,  g_W1h);
    cudaGetSymbolAddress(&w2h,  g_W2h);
    cudaGetSymbolAddress(&w3h,  g_W3h);
    cudaGetSymbolAddress(&pcnt, g_ccnt);

    cudaFuncSetAttribute((const void*)mlp_fused,
                         cudaFuncAttributeMaxDynamicSharedMemorySize, MLP_SMEM);

    cudaMemsetAsync(pcnt, 0, (size_t)(GRIDC + 1) * sizeof(int));
    setup_kernel<<<358, 256>>>(kp, trans, W1, W2, W3,
                               (__half*)w1h, (__half*)w2h, (__half*)w3h);
    knn_query<<<NPTS / 8, 256>>>(pts, kp);
    feat_kernel<<<NPTS / 8, 256>>>(pts, kp, nbr, rest, lat, out);
    mlp_fused<<<NPTS / MROWS, 256, MLP_SMEM>>>(
        (const __half*)pFH, (const __half*)w1h, (const __half*)w2h,
        (const __half*)w3h, b1, b2, b3, out);
}

// round 17
// speedup vs baseline: 5.6708x; 1.0458x over previous
#include <cuda_runtime.h>
#include <cuda_fp16.h>
#include <cstdint>
#include <math.h>

#define NV      6890
#define NPTS    16384
#define LDF     704

// ---- spatial grid for KNN ----
#define GRIDN   64
#define GRIDC   (GRIDN * GRIDN * GRIDN)
#define GLO     (-5.0f)
#define GH      0.15625f
#define GINV    6.4f
#define CELLCAP 8
#define OVFCAP  2048

// ---------------- scratch (device globals) -----------------------------------
__device__ __align__(16) __half  g_featH[(size_t)NPTS * LDF];
__device__ __align__(16) __half  g_W1h[(size_t)256 * LDF];
__device__ __align__(16) __half  g_W2h[(size_t)256 * 256];
__device__ __align__(16) __half  g_W3h[(size_t)256 * 256];
__device__ float                 g_Rinv[NV * 9];
__device__ __align__(16) float4  g_cell[(size_t)GRIDC * CELLCAP];
__device__ int                   g_ccnt[GRIDC + 1];   // [GRIDC] = overflow count; memset 0
__device__ __align__(16) float4  g_ovf[OVFCAP];

// ======================= small PTX helpers ===================================
__device__ __forceinline__ uint32_t smem_u32(const void* p) {
    uint32_t a;
    asm("{ .reg .u64 t; cvta.to.shared.u64 t, %1; cvt.u32.u64 %0, t; }" : "=r"(a) : "l"(p));
    return a;
}
__device__ __forceinline__ void cpa16(uint32_t dst, const void* src) {
    asm volatile("cp.async.cg.shared.global [%0], [%1], 16;" :: "r"(dst), "l"(src));
}
#define CPA_COMMIT() asm volatile("cp.async.commit_group;" ::: "memory")

__device__ __forceinline__ void ldm4(uint32_t* r, uint32_t addr) {
    asm volatile("ldmatrix.sync.aligned.m8n8.x4.shared.b16 {%0,%1,%2,%3}, [%4];"
                 : "=r"(r[0]), "=r"(r[1]), "=r"(r[2]), "=r"(r[3]) : "r"(addr));
}
__device__ __forceinline__ void mma16816(float* c, const uint32_t* a, uint32_t b0, uint32_t b1) {
    asm volatile(
        "mma.sync.aligned.m16n8k16.row.col.f32.f16.f16.f32 "
        "{%0,%1,%2,%3}, {%4,%5,%6,%7}, {%8,%9}, {%0,%1,%2,%3};"
        : "+f"(c[0]), "+f"(c[1]), "+f"(c[2]), "+f"(c[3])
        : "r"(a[0]), "r"(a[1]), "r"(a[2]), "r"(a[3]), "r"(b0), "r"(b1));
}

// ---------------- accurate fp32 sincos (no FP64) -----------------------------
__device__ __forceinline__ void sincos_acc(float x, float* s, float* c) {
    const float C1 = 6.28125f;
    const float C2 = (float)1.9353071795864769e-3;
    const float C3 = (float)(6.283185307179586476925286766559 - 6.28125 -
                             (double)((float)1.9353071795864769e-3));
    float q = rintf(x * 0.15915494309189535f);
    float r = fmaf(q, -C1, x);
    r = fmaf(q, -C2, r);
    r = fmaf(q, -C3, r);
    sincosf(r, s, c);
}

// ============ kernel 1: setup (grid build | invert | transpose) ===============
__global__ __launch_bounds__(256) void setup_kernel(
    const float* __restrict__ kp,
    const float* __restrict__ trans,
    const float* __restrict__ W1, const float* __restrict__ W2,
    const float* __restrict__ W3,
    __half* __restrict__ W1h, __half* __restrict__ W2h, __half* __restrict__ W3h)
{
    __shared__ float tile[32][33];
    const int b   = blockIdx.x;
    const int tid = threadIdx.x;

    if (b < 27) {
        int v = b * 256 + tid;
        if (v >= NV) return;
        float kx = kp[v*3], ky = kp[v*3+1], kz = kp[v*3+2];
        int cx = (int)floorf((kx - GLO) * GINV);
        int cy = (int)floorf((ky - GLO) * GINV);
        int cz = (int)floorf((kz - GLO) * GINV);
        float4 rec = make_float4(kx, ky, kz, __int_as_float(v));
        if ((unsigned)cx < GRIDN && (unsigned)cy < GRIDN && (unsigned)cz < GRIDN) {
            int c = (cz * GRIDN + cy) * GRIDN + cx;
            int s = atomicAdd(&g_ccnt[c], 1);
            if (s < CELLCAP) {
                g_cell[(size_t)c * CELLCAP + s] = rec;
            } else {
                int o = atomicAdd(&g_ccnt[GRIDC], 1);
                if (o < OVFCAP) g_ovf[o] = rec;
            }
        } else {
            int o = atomicAdd(&g_ccnt[GRIDC], 1);
            if (o < OVFCAP) g_ovf[o] = rec;
        }

    } else if (b < 54) {
        int v = (b - 27) * 256 + tid;
        if (v >= NV) return;
        float m[16];
#pragma unroll
        for (int k = 0; k < 16; k++) m[k] = trans[k * NV + v];

        float i0  =  m[5]*m[10]*m[15] - m[5]*m[11]*m[14] - m[9]*m[6]*m[15] + m[9]*m[7]*m[14] + m[13]*m[6]*m[11] - m[13]*m[7]*m[10];
        float i4  = -m[4]*m[10]*m[15] + m[4]*m[11]*m[14] + m[8]*m[6]*m[15] - m[8]*m[7]*m[14] - m[12]*m[6]*m[11] + m[12]*m[7]*m[10];
        float i8  =  m[4]*m[9]*m[15]  - m[4]*m[11]*m[13] - m[8]*m[5]*m[15] + m[8]*m[7]*m[13] + m[12]*m[5]*m[11] - m[12]*m[7]*m[9];
        float i12 = -m[4]*m[9]*m[14]  + m[4]*m[10]*m[13] + m[8]*m[5]*m[14] - m[8]*m[6]*m[13] - m[12]*m[5]*m[10] + m[12]*m[6]*m[9];
        float i1  = -m[1]*m[10]*m[15] + m[1]*m[11]*m[14] + m[9]*m[2]*m[15] - m[9]*m[3]*m[14] - m[13]*m[2]*m[11] + m[13]*m[3]*m[10];
        float i5  =  m[0]*m[10]*m[15] - m[0]*m[11]*m[14] - m[8]*m[2]*m[15] + m[8]*m[3]*m[14] + m[12]*m[2]*m[11] - m[12]*m[3]*m[10];
        float i9  = -m[0]*m[9]*m[15]  + m[0]*m[11]*m[13] + m[8]*m[1]*m[15] - m[8]*m[3]*m[13] - m[12]*m[1]*m[11] + m[12]*m[3]*m[9];
        float i2  =  m[1]*m[6]*m[15]  - m[1]*m[7]*m[14]  - m[5]*m[2]*m[15] + m[5]*m[3]*m[14] + m[13]*m[2]*m[7]  - m[13]*m[3]*m[6];
        float i6  = -m[0]*m[6]*m[15]  + m[0]*m[7]*m[14]  + m[4]*m[2]*m[15] - m[4]*m[3]*m[14] - m[12]*m[2]*m[7]  + m[12]*m[3]*m[6];
        float i10 =  m[0]*m[5]*m[15]  - m[0]*m[7]*m[13]  - m[4]*m[1]*m[15] + m[4]*m[3]*m[13] + m[12]*m[1]*m[7]  - m[12]*m[3]*m[5];

        float det = m[0]*i0 + m[1]*i4 + m[2]*i8 + m[3]*i12;
        float id  = 1.0f / det;
        float* R = g_Rinv + v * 9;
        R[0] = i0*id;  R[1] = i1*id;  R[2] = i2*id;
        R[3] = i4*id;  R[4] = i5*id;  R[5] = i6*id;
        R[6] = i8*id;  R[7] = i9*id;  R[8] = i10*id;

    } else {
        int u = b - 54;
        const float* W; __half* Wh; int K, ldk, kb, nb;
        if (u < 176)      { W = W1; Wh = W1h; K = 700; ldk = LDF; kb = (u % 22) * 32; nb = (u / 22) * 32; }
        else if (u < 240) { u -= 176; W = W2; Wh = W2h; K = 256; ldk = 256; kb = (u % 8) * 32; nb = (u / 8) * 32; }
        else              { u -= 240; W = W3; Wh = W3h; K = 256; ldk = 256; kb = (u % 8) * 32; nb = (u / 8) * 32; }

        int tx = tid & 31, ty = tid >> 5;
#pragma unroll
        for (int i = 0; i < 4; i++) {
            int k = kb + ty + i * 8;
            tile[ty + i * 8][tx] = (k < K) ? W[(size_t)k * 256 + nb + tx] : 0.0f;
        }
        __syncthreads();
#pragma unroll
        for (int i = 0; i < 4; i++) {
            int n = nb + ty + i * 8;
            Wh[(size_t)n * ldk + kb + tx] = __float2half_rn(tile[tx][ty + i * 8]);
        }
    }
}

// ============ kernel 2: fused grid-KNN + feature build (warp per point) ======
__global__ __launch_bounds__(256) void featknn_kernel(
    const float* __restrict__ pts, const float* __restrict__ kp,
    const int*   __restrict__ nbr, const float* __restrict__ rest,
    const float* __restrict__ lat, float* __restrict__ out)
{
    const int gw   = (blockIdx.x * blockDim.x + threadIdx.x) >> 5;
    const int lane = threadIdx.x & 31;
    if (gw >= NPTS) return;

    const float px = pts[gw*6], py = pts[gw*6+1], pz = pts[gw*6+2];

    int cx = min(max((int)floorf((px - GLO) * GINV), 0), GRIDN - 1);
    int cy = min(max((int)floorf((py - GLO) * GINV), 0), GRIDN - 1);
    int cz = min(max((int)floorf((pz - GLO) * GINV), 0), GRIDN - 1);

    unsigned long long best = ~0ull;

#pragma unroll
    for (int it = 0; it < 4; it++) {
        int s = lane + it * 32;
        if (s < 125) {
            int x = cx + (s % 5) - 2;
            int y = cy + ((s / 5) % 5) - 2;
            int z = cz + (s / 25) - 2;
            if ((unsigned)x < GRIDN && (unsigned)y < GRIDN && (unsigned)z < GRIDN) {
                int c = (z * GRIDN + y) * GRIDN + x;
                int cnt = min(g_ccnt[c], CELLCAP);
                const float4* cd = &g_cell[(size_t)c * CELLCAP];
                for (int j = 0; j < cnt; j++) {
                    float4 k = cd[j];
                    float dx = px - k.x, dy = py - k.y, dz = pz - k.z;
                    float d2 = fmaf(dx, dx, fmaf(dy, dy, dz * dz));
                    unsigned long long pk =
                        ((unsigned long long)__float_as_uint(d2) << 32) |
                        (unsigned int)__float_as_int(k.w);
                    if (pk < best) best = pk;
                }
            }
        }
    }
    {
        int n = min(g_ccnt[GRIDC], OVFCAP);
        for (int i = lane; i < n; i += 32) {
            float4 k = g_ovf[i];
            float dx = px - k.x, dy = py - k.y, dz = pz - k.z;
            float d2 = fmaf(dx, dx, fmaf(dy, dy, dz * dz));
            unsigned long long pk =
                ((unsigned long long)__float_as_uint(d2) << 32) |
                (unsigned int)__float_as_int(k.w);
            if (pk < best) best = pk;
        }
    }
    unsigned long long o;
    o = __shfl_xor_sync(0xffffffffu, best, 1);  if (o < best) best = o;
    o = __shfl_xor_sync(0xffffffffu, best, 2);  if (o < best) best = o;
    o = __shfl_xor_sync(0xffffffffu, best, 4);  if (o < best) best = o;
    o = __shfl_xor_sync(0xffffffffu, best, 8);  if (o < best) best = o;
    o = __shfl_xor_sync(0xffffffffu, best, 16); if (o < best) best = o;

    const float GUAR = 2.0f * GH;
    if ((uint32_t)(best >> 32) > __float_as_uint(GUAR * GUAR)) {
        for (int i = lane; i < NV; i += 32) {
            float dx = px - kp[i*3], dy = py - kp[i*3+1], dz = pz - kp[i*3+2];
            float d2 = fmaf(dx, dx, fmaf(dy, dy, dz * dz));
            unsigned long long pk =
                ((unsigned long long)__float_as_uint(d2) << 32) | (unsigned int)i;
            if (pk < best) best = pk;
        }
        o = __shfl_xor_sync(0xffffffffu, best, 1);  if (o < best) best = o;
        o = __shfl_xor_sync(0xffffffffu, best, 2);  if (o < best) best = o;
        o = __shfl_xor_sync(0xffffffffu, best, 4);  if (o < best) best = o;
        o = __shfl_xor_sync(0xffffffffu, best, 8);  if (o < best) best = o;
        o = __shfl_xor_sync(0xffffffffu, best, 16); if (o < best) best = o;
    }
    const int kidx = (int)(best & 0xFFFFFFFFull);

    // ---------- feature build ----------
    int vj = (lane < 7) ? nbr[kidx*7 + lane] : 0;
    int j  = (lane < 21) ? (lane / 3) : ((lane < 28) ? (lane - 21) : 0);
    int v  = __shfl_sync(0xffffffffu, vj, j);

    float vf = 0.0f;
    if (lane < 21) {
        vf = rest[v*3 + (lane % 3)];
    } else if (lane < 28) {
        float dx = px - kp[v*3], dy = py - kp[v*3+1], dz = pz - kp[v*3+2];
        vf = sqrtf(dx*dx + dy*dy + dz*dz);
    }

    size_t base = (size_t)gw * LDF;
    if (lane < 28) {
        g_featH[base + lane] = __float2half_rn(vf);
        float s, c;
        sincos_acc(vf, &s, &c);
#pragma unroll
        for (int k = 0; k < 10; k++) {
            g_featH[base + 28  + k*28 + lane] = __float2half_rn(s);
            g_featH[base + 308 + k*28 + lane] = __float2half_rn(c);
            float sn = 2.0f * s * c;
            float cn = fmaf(-2.0f * s, s, 1.0f);
            s = sn; c = cn;
        }
    }
    if (lane < 4) g_featH[base + 700 + lane] = __float2half_rn(0.0f);

#pragma unroll
    for (int it = 0; it < 4; it++) {
        int l  = it * 32 + lane;
        int jj = (l < 112) ? (l >> 4) : 0;
        int vv = __shfl_sync(0xffffffffu, vj, jj);
        if (l < 112) g_featH[base + 588 + l] = __float2half_rn(lat[vv*16 + (l & 15)]);
    }

    if (lane == 0) {
        float dx = px - kp[kidx*3], dy = py - kp[kidx*3+1], dz = pz - kp[kidx*3+2];
        const float* R = g_Rinv + kidx * 9;
        float d0 = R[0]*dx + R[1]*dy + R[2]*dz;
        float d1 = R[3]*dx + R[4]*dy + R[5]*dz;
        float d2 = R[6]*dx + R[7]*dy + R[8]*dz;
        float nn = sqrtf(d0*d0 + d1*d1 + d2*d2);
        float iv = 1.0f / fmaxf(nn, 1e-12f);
        d0 *= iv; d1 *= iv; d2 *= iv;
        float* op = out + (size_t)gw * 283 + 256;
        op[0] = d0; op[1] = d1; op[2] = d2;
        float dir[3] = {d0, d1, d2};
#pragma unroll
        for (int c = 0; c < 3; c++) {
            float s, cc;
            sincos_acc(dir[c], &s, &cc);
#pragma unroll
            for (int k = 0; k < 4; k++) {
                op[3  + k*3 + c] = s;
                op[15 + k*3 + c] = cc;
                float sn = 2.0f * s * cc;
                float cn = fmaf(-2.0f * s, s, 1.0f);
                s = sn; cc = cn;
            }
        }
    }
}

// ---------------- kernel 3: fused 3-layer MLP, 1 sync/chunk + epi guards -----
#define PADH    40
#define MROWS   64
#define ATILE   (MROWS * PADH * 2)         // 5120 B
#define BTILE   (256 * PADH * 2)           // 20480 B
#define BUFB    (ATILE + BTILE)            // 25600 B
#define SM_H    (2 * BUFB)                 // 51200
#define HCHUNK  (MROWS * PADH)
#define MLP_SMEM (SM_H + 8 * HCHUNK * 2)   // 92160 B

__global__ __launch_bounds__(256, 2) void mlp_fused(
    const __half* __restrict__ feat,
    const __half* __restrict__ W1, const __half* __restrict__ W2,
    const __half* __restrict__ W3,
    const float* __restrict__ b1, const float* __restrict__ b2,
    const float* __restrict__ b3,
    float* __restrict__ out)
{
    extern __shared__ char sm[];
    const int tid  = threadIdx.x;
    const int wid  = tid >> 5, lane = tid & 31;
    const int g    = lane >> 2, t = lane & 3;
    const int m0   = blockIdx.x * MROWS;
    const int m0w  = (wid >> 2) * 32, n0w = (wid & 3) * 64;
    const uint32_t smb = smem_u32(sm);
    const uint32_t sH  = smb + SM_H;
    __half* Hs = (__half*)(sm + SM_H);

    const int arow = lane & 15;
    const int asel = (lane >> 4) << 3;
    const int brow = (lane & 7) + ((lane & 16) ? 8 : 0);
    const int bsel = (lane & 8) ? 8 : 0;

    float acc[2][8][4];

    auto zacc = [&]() {
#pragma unroll
        for (int mi = 0; mi < 2; mi++)
#pragma unroll
            for (int ni = 0; ni < 8; ni++)
#pragma unroll
                for (int q = 0; q < 4; q++) acc[mi][ni][q] = 0.0f;
    };

    auto issueA = [&](int ch) {
        const int k0 = ch * 32;
        uint32_t base = smb + (ch & 1) * BUFB;
        int r = tid >> 2, c = (tid & 3) * 8;
        cpa16(base + (uint32_t)(r * PADH + c) * 2, feat + (size_t)(m0 + r) * LDF + k0 + c);
    };
    auto issueB = [&](const __half* W, int ldw, int ch) {
        const int k0 = ch * 32;
        uint32_t base = smb + (ch & 1) * BUFB + ATILE;
#pragma unroll
        for (int i = 0; i < 4; i++) {
            int s = tid + i * 256;
            int r = s >> 2, c = (s & 3) * 8;
            cpa16(base + (uint32_t)(r * PADH + c) * 2, W + (size_t)r * ldw + k0 + c);
        }
    };
    auto compute = [&](uint32_t sA, uint32_t sB) {
#pragma unroll
        for (int ks = 0; ks < 2; ks++) {
            const int kc = ks * 16;
            uint32_t ah[2][4];
#pragma unroll
            for (int mi = 0; mi < 2; mi++)
                ldm4(ah[mi], sA + (uint32_t)((m0w + mi * 16 + arow) * PADH + kc + asel) * 2);
#pragma unroll
            for (int ph = 0; ph < 2; ph++) {
                uint32_t bh[2][4];
#pragma unroll
                for (int pp = 0; pp < 2; pp++) {
                    int p = ph * 2 + pp;
                    ldm4(bh[pp], sB + (uint32_t)((n0w + p * 16 + brow) * PADH + kc + bsel) * 2);
                }
#pragma unroll
                for (int pp = 0; pp < 2; pp++)
#pragma unroll
                    for (int q = 0; q < 2; q++)
#pragma unroll
                        for (int mi = 0; mi < 2; mi++)
                            mma16816(acc[mi][(ph*2+pp)*2+q], ah[mi], bh[pp][q*2], bh[pp][q*2+1]);
            }
        }
    };
    auto epi_smem = [&](const float* bias) {
#pragma unroll
        for (int mi = 0; mi < 2; mi++) {
            int row = m0w + mi * 16 + g;
#pragma unroll
            for (int ni = 0; ni < 8; ni++) {
                int col = n0w + ni * 8 + 2 * t;
                float c0 = bias[col], c1 = bias[col + 1];
                float v0 = fmaxf(acc[mi][ni][0] + c0, 0.f);
                float v1 = fmaxf(acc[mi][ni][1] + c1, 0.f);
                float v2 = fmaxf(acc[mi][ni][2] + c0, 0.f);
                float v3 = fmaxf(acc[mi][ni][3] + c1, 0.f);
                int blk = (col >> 5) * HCHUNK, cc = col & 31;
                *(__half2*)&Hs[blk + row * PADH + cc] =
                    __halves2half2(__float2half_rn(v0), __float2half_rn(v1));
                *(__half2*)&Hs[blk + (row + 8) * PADH + cc] =
                    __halves2half2(__float2half_rn(v2), __float2half_rn(v3));
            }
        }
    };

    // ===== layer 1: feat(704) -> h1 =====
    zacc();
    issueA(0); issueB(W1, LDF, 0); CPA_COMMIT();
    for (int ch = 0; ch < 22; ch++) {
        asm volatile("cp.async.wait_group 0;" ::: "memory");
        __syncthreads();
        if (ch + 1 < 22) { issueA(ch + 1); issueB(W1, LDF, ch + 1); CPA_COMMIT(); }
        uint32_t base = smb + (ch & 1) * BUFB;
        compute(base, base + ATILE);
    }
    __syncthreads();            // guard: epi writes Hs; no concurrent Hs readers in L1,
    epi_smem(b1);               // but keeps warps aligned entering layer 2

    // ===== layer 2: h1 -> h2 =====
    zacc();
    issueB(W2, 256, 0); CPA_COMMIT();
    for (int ch = 0; ch < 8; ch++) {
        asm volatile("cp.async.wait_group 0;" ::: "memory");
        __syncthreads();        // orders epi Hs writes (ch==0) before Hs reads
        if (ch + 1 < 8) { issueB(W2, 256, ch + 1); CPA_COMMIT(); }
        compute(sH + (uint32_t)ch * HCHUNK * 2, smb + (ch & 1) * BUFB + ATILE);
    }
    __syncthreads();            // RACE FIX: all warps finish reading Hs (compute ch=7)
    epi_smem(b2);               // before any warp overwrites shared Hs rows

    // ===== layer 3: h2 -> out =====
    zacc();
    issueB(W3, 256, 0); CPA_COMMIT();
    for (int ch = 0; ch < 8; ch++) {
        asm volatile("cp.async.wait_group 0;" ::: "memory");
        __syncthreads();        // orders epi(b2) Hs writes before reads
        if (ch + 1 < 8) { issueB(W3, 256, ch + 1); CPA_COMMIT(); }
        compute(sH + (uint32_t)ch * HCHUNK * 2, smb + (ch & 1) * BUFB + ATILE);
    }
#pragma unroll
    for (int mi = 0; mi < 2; mi++) {
        int row = m0 + m0w + mi * 16 + g;
#pragma unroll
        for (int ni = 0; ni < 8; ni++) {
            int col = n0w + ni * 8 + 2 * t;
            float c0 = b3[col], c1 = b3[col + 1];
            out[(size_t)row * 283 + col]           = acc[mi][ni][0] + c0;
            out[(size_t)row * 283 + col + 1]       = acc[mi][ni][1] + c1;
            out[(size_t)(row + 8) * 283 + col]     = acc[mi][ni][2] + c0;
            out[(size_t)(row + 8) * 283 + col + 1] = acc[mi][ni][3] + c1;
        }
    }
}

// ---------------- launch -----------------------------------------------------
extern "C" void kernel_launch(void* const* d_in, const int* in_sizes, int n_in,
                              void* d_out, int out_size) {
    const float* pts   = (const float*)d_in[0];
    const float* kp    = (const float*)d_in[1];
    const float* trans = (const float*)d_in[2];
    const int*   nbr   = (const int*)  d_in[3];
    const float* rest  = (const float*)d_in[4];
    const float* lat   = (const float*)d_in[5];
    const float* W1    = (const float*)d_in[6];
    const float* b1    = (const float*)d_in[7];
    const float* W2    = (const float*)d_in[8];
    const float* b2    = (const float*)d_in[9];
    const float* W3    = (const float*)d_in[10];
    const float* b3    = (const float*)d_in[11];
    float*       out   = (float*)d_out;

    void *pFH, *w1h, *w2h, *w3h, *pcnt;
    cudaGetSymbolAddress(&pFH,  g_featH);
    cudaGetSymbolAddress(&w1h,  g_W1h);
    cudaGetSymbolAddress(&w2h,  g_W2h);
    cudaGetSymbolAddress(&w3h,  g_W3h);
    cudaGetSymbolAddress(&pcnt, g_ccnt);

    cudaFuncSetAttribute((const void*)mlp_fused,
                         cudaFuncAttributeMaxDynamicSharedMemorySize, MLP_SMEM);

    cudaMemsetAsync(pcnt, 0, (size_t)(GRIDC + 1) * sizeof(int));
    setup_kernel<<<358, 256>>>(kp, trans, W1, W2, W3,
                               (__half*)w1h, (__half*)w2h, (__half*)w3h);
    featknn_kernel<<<NPTS / 8, 256>>>(pts, kp, nbr, rest, lat, out);
    mlp_fused<<<NPTS / MROWS, 256, MLP_SMEM>>>(
        (const __half*)pFH, (const __half*)w1h, (const __half*)w2h,
        (const __half*)w3h, b1, b2, b3, out);
}